// round 10
// baseline (speedup 1.0000x reference)
#include <cuda_runtime.h>
#include <cuda_bf16.h>
#include <math.h>
#include <stdint.h>

// Problem constants
#define BB 256
#define SS 512
#define KK 20
#define DD 256
#define PITCHB 528   // bytes per bf16 row (264 elems): odd 16B count -> ldmatrix conflict-free
#define KVP 132      // kV table pitch (f32)

// Precomputed scratch (static device globals: allocation-free)
__device__ float g_xw[(size_t)BB * SS * DD];   // xW[b][s][e]
__device__ float g_xk[(size_t)BB * SS * KK];   // x.keys[b][s][k]

// ================= PTX helpers =================
__device__ __forceinline__ uint32_t smem_u32(const void* p) {
    uint32_t a;
    asm("{ .reg .u64 t; cvta.to.shared.u64 t, %1; cvt.u32.u64 %0, t; }" : "=r"(a) : "l"(p));
    return a;
}
__device__ __forceinline__ uint32_t cluster_rank() {
    uint32_t r;
    asm("mov.u32 %0, %%cluster_ctarank;" : "=r"(r));
    return r;
}
#define CLUSTER_SYNC() do { \
    asm volatile("barrier.cluster.arrive.aligned;" ::: "memory"); \
    asm volatile("barrier.cluster.wait.aligned;" ::: "memory"); \
} while (0)

#define LDSM4(r, addr) \
    asm volatile("ldmatrix.sync.aligned.m8n8.x4.shared.b16 {%0,%1,%2,%3}, [%4];" \
        : "=r"((r)[0]), "=r"((r)[1]), "=r"((r)[2]), "=r"((r)[3]) : "r"(addr))
#define LDSM2(r, addr) \
    asm volatile("ldmatrix.sync.aligned.m8n8.x2.shared.b16 {%0,%1}, [%2];" \
        : "=r"((r)[0]), "=r"((r)[1]) : "r"(addr))

#define MMA16816(c, a, b0, b1) \
    asm volatile("mma.sync.aligned.m16n8k16.row.col.f32.bf16.bf16.f32 " \
        "{%0,%1,%2,%3}, {%4,%5,%6,%7}, {%8,%9}, {%0,%1,%2,%3};" \
        : "+f"((c)[0]), "+f"((c)[1]), "+f"((c)[2]), "+f"((c)[3]) \
        : "r"((a)[0]), "r"((a)[1]), "r"((a)[2]), "r"((a)[3]), "r"(b0), "r"(b1))

// ================= shared memory layout (rnn kernel) =================
struct MiscS {
    float red[8][2 * KK];
    float tot[2 * KK];
    float rpart[2 * KK];
    float gbuf[KK];
    float rbuf[KK];
    unsigned short slist[SS];
    int wcnt[8];
};
#define OFF_ULO 0                                 // U^T lo [128 e][256 d] bf16 (staged hi first)
#define OFF_HHI (128 * PITCHB)                    // h hi tile [24 k][256 d] bf16
#define OFF_HLO (OFF_HHI + 24 * PITCHB)
#define OFF_KV  (OFF_HLO + 24 * PITCHB)           // kV [20][KVP] f32
#define OFF_MISC (OFF_KV + KK * KVP * 4)
#define SMEM_TOT ((int)(OFF_MISC + sizeof(MiscS)))

// ================= shared memory layout (xw kernel) =================
#define XW_OFF_WT 0                               // W^T half [128 e][256 d] bf16 (hi or lo pass)
#define XW_OFF_XHI (128 * PITCHB)                 // X tile hi [64 s][256 d]
#define XW_OFF_XLO (XW_OFF_XHI + 64 * PITCHB)
#define XW_SMEM_TOT (XW_OFF_XLO + 64 * PITCHB)

// ================= kernel 1: xW via HMMA (bf16 hi/lo, 3 passes) =================
// Grid: 2048 CTAs; each computes xW for 64 s-rows x 256 e of one batch chunk.
// Warp layout: (w&3) -> 16-s m-tile, (w>>2) -> 64-e group (8 n-tiles). FULL e coverage.
__global__ void __launch_bounds__(256) xw_mma_kernel(const float* __restrict__ X,
                                                     const float* __restrict__ W) {
    extern __shared__ __align__(16) unsigned char smw[];
    const int tid = threadIdx.x;
    const int lane = tid & 31, w = tid >> 5;
    const int cta = blockIdx.x;                 // 2048 = BB * (SS/64)
    const int b = cta >> 3;
    const int s0 = (cta & 7) * 64;
    const uint32_t smb = smem_u32(smw);

    // stage X tile [64 s][256 d] bf16 hi/lo
    for (int idx = tid; idx < 64 * DD; idx += 256) {
        const int ss = idx >> 8, d = idx & 255;
        const float f = X[((size_t)(b * SS + s0 + ss)) * DD + d];
        const __nv_bfloat16 hi = __float2bfloat16(f);
        const __nv_bfloat16 lo = __float2bfloat16(f - __bfloat162float(hi));
        *(unsigned short*)(smw + XW_OFF_XHI + ss * PITCHB + d * 2) = __bfloat16_as_ushort(hi);
        *(unsigned short*)(smw + XW_OFF_XLO + ss * PITCHB + d * 2) = __bfloat16_as_ushort(lo);
    }

    const int sr0 = (w & 3) * 16;
    const int ec0 = (w >> 2) * 64;               // 64 e per warp -> 8 n-tiles
    const uint32_t aoff = (uint32_t)(sr0 + (lane & 7) + ((lane >> 3) & 1) * 8) * PITCHB
                        + (uint32_t)((lane >> 4) & 1) * 16;
    const int gr = lane >> 2, gc = (lane & 3) * 2;
    // B ldmatrix per 16-e block bt: rows ec0+16*bt + (lane&7) + ((lane>>4)&1)*8
    uint32_t bOff[4];
#pragma unroll
    for (int bt = 0; bt < 4; bt++)
        bOff[bt] = (uint32_t)(ec0 + 16 * bt + (lane & 7) + ((lane >> 4) & 1) * 8) * PITCHB
                 + (uint32_t)((lane >> 3) & 1) * 16;

    for (int half = 0; half < 2; half++) {
        // stage W^T half [128 e][256 d] HI
        __syncthreads();
        for (int idx = tid; idx < 128 * DD; idx += 256) {
            const int el = idx & 127, d = idx >> 7;
            const float f = W[(size_t)d * DD + half * 128 + el];
            *(unsigned short*)(smw + XW_OFF_WT + el * PITCHB + d * 2) =
                __bfloat16_as_ushort(__float2bfloat16(f));
        }
        __syncthreads();

        float c[8][4];   // 8 n-tiles of 8 e = 64 e per warp
#pragma unroll
        for (int nt = 0; nt < 8; nt++)
#pragma unroll
            for (int q = 0; q < 4; q++) c[nt][q] = 0.f;

        // pass 1+2: Xhi*Whi + Xlo*Whi
#pragma unroll 2
        for (int kc = 0; kc < 16; kc++) {
            const uint32_t dofs = (uint32_t)kc * 32;
            uint32_t ah[4], al[4];
            LDSM4(ah, smb + XW_OFF_XHI + aoff + dofs);
            LDSM4(al, smb + XW_OFF_XLO + aoff + dofs);
#pragma unroll
            for (int bt = 0; bt < 4; bt++) {
                uint32_t bh[4];
                LDSM4(bh, smb + XW_OFF_WT + bOff[bt] + dofs);
                MMA16816(c[2 * bt], ah, bh[0], bh[1]);
                MMA16816(c[2 * bt + 1], ah, bh[2], bh[3]);
                MMA16816(c[2 * bt], al, bh[0], bh[1]);
                MMA16816(c[2 * bt + 1], al, bh[2], bh[3]);
            }
        }

        // restage W^T half LO
        __syncthreads();
        for (int idx = tid; idx < 128 * DD; idx += 256) {
            const int el = idx & 127, d = idx >> 7;
            const float f = W[(size_t)d * DD + half * 128 + el];
            const __nv_bfloat16 hi = __float2bfloat16(f);
            *(unsigned short*)(smw + XW_OFF_WT + el * PITCHB + d * 2) =
                __bfloat16_as_ushort(__float2bfloat16(f - __bfloat162float(hi)));
        }
        __syncthreads();

        // pass 3: Xhi*Wlo
#pragma unroll 2
        for (int kc = 0; kc < 16; kc++) {
            const uint32_t dofs = (uint32_t)kc * 32;
            uint32_t ah[4];
            LDSM4(ah, smb + XW_OFF_XHI + aoff + dofs);
#pragma unroll
            for (int bt = 0; bt < 4; bt++) {
                uint32_t bl[4];
                LDSM4(bl, smb + XW_OFF_WT + bOff[bt] + dofs);
                MMA16816(c[2 * bt], ah, bl[0], bl[1]);
                MMA16816(c[2 * bt + 1], ah, bl[2], bl[3]);
            }
        }

        // write out C[s][e] frags
#pragma unroll
        for (int nt = 0; nt < 8; nt++) {
#pragma unroll
            for (int j = 0; j < 2; j++) {
                const int eo = half * 128 + ec0 + 8 * nt + gc + j;
                g_xw[((size_t)(b * SS + s0 + sr0 + gr)) * DD + eo] = c[nt][j];
                g_xw[((size_t)(b * SS + s0 + sr0 + 8 + gr)) * DD + eo] = c[nt][2 + j];
            }
        }
    }
}

// ================= kernel 1b: xk[b][s][k] = x . keys[b][k] =================
__global__ void __launch_bounds__(256) xk_kernel(const float* __restrict__ X,
                                                 const float* __restrict__ keys) {
    const int b = blockIdx.x >> 6;
    const int s = ((blockIdx.x & 63) << 3) + (threadIdx.x >> 5);
    const int lane = threadIdx.x & 31;
    const float* x = X + ((size_t)b * SS + s) * DD;
    const float* kb = keys + (size_t)b * KK * DD;

    float xr[8];
#pragma unroll
    for (int c = 0; c < 8; c++) xr[c] = x[lane + 32 * c];

    float pk[KK];
#pragma unroll
    for (int k = 0; k < KK; k++) {
        float p = 0.f;
#pragma unroll
        for (int c = 0; c < 8; c++) p = fmaf(xr[c], kb[k * DD + lane + 32 * c], p);
        pk[k] = p;
    }
#pragma unroll
    for (int o = 16; o; o >>= 1)
#pragma unroll
        for (int k = 0; k < KK; k++) pk[k] += __shfl_xor_sync(0xffffffffu, pk[k], o);

    if (lane < KK)
        g_xk[((size_t)b * SS + s) * KK + lane] = pk[lane];
}

// ================= kernel 2: HMMA recurrent kernel (proven R7 version) =================
__global__ void __launch_bounds__(256, 2) __cluster_dims__(2, 1, 1)
rnn_mma_kernel(const float* __restrict__ X, const int* __restrict__ mask,
               const float* __restrict__ keys, const float* __restrict__ U,
               const float* __restrict__ V, float* __restrict__ out) {
    extern __shared__ __align__(16) unsigned char smraw[];
    MiscS* ms = (MiscS*)(smraw + OFF_MISC);
    float* kVs = (float*)(smraw + OFF_KV);

    const int tid = threadIdx.x;
    const int lane = tid & 31, w = tid >> 5;
    const int b = blockIdx.x >> 1;
    const uint32_t rank = cluster_rank();
    const uint32_t smbase = smem_u32(smraw);

    const int e0 = w * 16;
    const int gr = lane >> 2;
    const int gc = (lane & 3) * 2;
    const int el0 = e0 + gr;
    const int el1 = e0 + 8 + gr;
    const int eg0 = (int)rank * 128 + el0;
    const int eg1 = (int)rank * 128 + el1;

    // ---- mask compaction ----
    int n_act = 0;
    {
        int total = 0;
        for (int r = 0; r < 2; r++) {
            const int idx = r * 256 + tid;
            const int m = (mask[b * SS + idx] != 0);
            const unsigned bal = __ballot_sync(0xffffffffu, m);
            const int pre = __popc(bal & ((1u << lane) - 1));
            if (lane == 0) ms->wcnt[w] = __popc(bal);
            __syncthreads();
            int woff = 0;
            for (int ww = 0; ww < w; ww++) woff += ms->wcnt[ww];
            if (m) ms->slist[total + woff + pre] = (unsigned short)idx;
            int rt = 0;
#pragma unroll
            for (int ww = 0; ww < 8; ww++) rt += ms->wcnt[ww];
            total += rt;
            __syncthreads();
        }
        n_act = total;
    }

    // ---- stage U^T HI, preload A frags, overwrite with LO ----
    for (int idx = tid; idx < 128 * DD; idx += 256) {
        const int el = idx & 127, d = idx >> 7;
        const float f = U[(size_t)d * DD + rank * 128 + el];
        *(unsigned short*)(smraw + OFF_ULO + el * PITCHB + d * 2) =
            __bfloat16_as_ushort(__float2bfloat16(f));
    }
    __syncthreads();

    const uint32_t aoff = (uint32_t)(e0 + (lane & 7) + ((lane >> 3) & 1) * 8) * PITCHB
                        + (uint32_t)((lane >> 4) & 1) * 16;
    uint32_t uh[16][4];
#pragma unroll
    for (int kc = 0; kc < 16; kc++)
        LDSM4(uh[kc], smbase + OFF_ULO + aoff + (uint32_t)kc * 32);
    __syncthreads();

    for (int idx = tid; idx < 128 * DD; idx += 256) {
        const int el = idx & 127, d = idx >> 7;
        const float f = U[(size_t)d * DD + rank * 128 + el];
        const __nv_bfloat16 hi = __float2bfloat16(f);
        *(unsigned short*)(smraw + OFF_ULO + el * PITCHB + d * 2) =
            __bfloat16_as_ushort(__float2bfloat16(f - __bfloat162float(hi)));
    }

    // zero h tiles
    {
        const uint4 z = make_uint4(0, 0, 0, 0);
        uint4* p = (uint4*)(smraw + OFF_HHI);
        for (int i = tid; i < (2 * 24 * PITCHB) / 16; i += 256) p[i] = z;
    }

    // kV table
    {
        const int kh = tid >> 7, el = tid & 127;
        float kvv[10];
#pragma unroll
        for (int j = 0; j < 10; j++) kvv[j] = 0.f;
        const float* kr = keys + (size_t)b * KK * DD + (size_t)kh * 10 * DD;
#pragma unroll 4
        for (int d = 0; d < DD; d++) {
            const float vv = V[(size_t)d * DD + rank * 128 + el];
#pragma unroll
            for (int j = 0; j < 10; j++) kvv[j] = fmaf(kr[j * DD + d], vv, kvv[j]);
        }
#pragma unroll
        for (int j = 0; j < 10; j++) kVs[(kh * 10 + j) * KVP + el] = kvv[j];
    }

    if (tid < KK && n_act > 0)
        ms->gbuf[tid] = 1.f / (1.f + __expf(-g_xk[((size_t)b * SS + ms->slist[0]) * KK + tid]));
    __syncthreads();
    CLUSTER_SYNC();

    uint32_t peer_base;
    asm("mapa.shared::cluster.u32 %0, %1, %2;" : "=r"(peer_base) : "r"(smbase), "r"(rank ^ 1u));
    const uint32_t peer_rpart = peer_base + OFF_MISC + (uint32_t)offsetof(MiscS, rpart);

    const uint32_t bOff4 = (uint32_t)(8 * ((lane >> 4) & 1) + (lane & 7)) * PITCHB
                         + (uint32_t)((lane >> 3) & 1) * 16;
    const uint32_t bOff2 = (uint32_t)(16 + (lane & 7)) * PITCHB
                         + (uint32_t)((lane >> 3) & 1) * 16;
    const uint32_t hhi = smbase + OFF_HHI, hlo = smbase + OFF_HLO;
    const uint32_t ulo = smbase + OFF_ULO;

    for (int i = 0; i < n_act; i++) {
        const int s = ms->slist[i];
        const bool hasn = (i + 1 < n_act);
        const int sn = hasn ? (int)ms->slist[i + 1] : 0;
        const float xw0 = g_xw[((size_t)b * SS + s) * DD + eg0];
        const float xw1 = g_xw[((size_t)b * SS + s) * DD + eg1];
        float xn0 = 0.f, xn1 = 0.f;
        if (hasn) {
            xn0 = X[((size_t)b * SS + sn) * DD + eg0];
            xn1 = X[((size_t)b * SS + sn) * DD + eg1];
        }

        float c[3][4];
#pragma unroll
        for (int nt = 0; nt < 3; nt++)
#pragma unroll
            for (int q = 0; q < 4; q++) c[nt][q] = 0.f;

#pragma unroll
        for (int kc = 0; kc < 16; kc++) {
            const uint32_t dofs = (uint32_t)kc * 32;
            uint32_t bh[4], b2[2], al[4], bl[4], bl2[2];
            LDSM4(bh, hhi + bOff4 + dofs);
            LDSM2(b2, hhi + bOff2 + dofs);
            LDSM4(al, ulo + aoff + dofs);
            MMA16816(c[0], uh[kc], bh[0], bh[1]);
            MMA16816(c[1], uh[kc], bh[2], bh[3]);
            MMA16816(c[2], uh[kc], b2[0], b2[1]);
            MMA16816(c[0], al, bh[0], bh[1]);
            MMA16816(c[1], al, bh[2], bh[3]);
            MMA16816(c[2], al, b2[0], b2[1]);
            LDSM4(bl, hlo + bOff4 + dofs);
            LDSM2(bl2, hlo + bOff2 + dofs);
            MMA16816(c[0], uh[kc], bl[0], bl[1]);
            MMA16816(c[1], uh[kc], bl[2], bl[3]);
            MMA16816(c[2], uh[kc], bl2[0], bl2[1]);
        }

        float sq6[6], du6[6];
#pragma unroll
        for (int nt = 0; nt < 3; nt++) {
#pragma unroll
            for (int j = 0; j < 2; j++) {
                const int k = 8 * nt + gc + j;
                const bool val = (k < KK);
                const int kk = val ? k : 0;
                const float gv = val ? ms->gbuf[kk] : 0.f;
                const float kv0 = kVs[kk * KVP + el0];
                const float kv1 = kVs[kk * KVP + el1];
                float u0 = 0.f, u1 = 0.f;
                if (val) {
                    const unsigned short h0h = *(unsigned short*)(smraw + OFF_HHI + kk * PITCHB + eg0 * 2);
                    const unsigned short h0l = *(unsigned short*)(smraw + OFF_HLO + kk * PITCHB + eg0 * 2);
                    const unsigned short h1h = *(unsigned short*)(smraw + OFF_HHI + kk * PITCHB + eg1 * 2);
                    const unsigned short h1l = *(unsigned short*)(smraw + OFF_HLO + kk * PITCHB + eg1 * 2);
                    const float ho0 = __bfloat162float(__ushort_as_bfloat16(h0h)) +
                                      __bfloat162float(__ushort_as_bfloat16(h0l));
                    const float ho1 = __bfloat162float(__ushort_as_bfloat16(h1h)) +
                                      __bfloat162float(__ushort_as_bfloat16(h1l));
                    u0 = ho0 + gv * fmaxf(c[nt][j] + kv0 + xw0, 0.f);
                    u1 = ho1 + gv * fmaxf(c[nt][2 + j] + kv1 + xw1, 0.f);
                }
                c[nt][j] = u0;
                c[nt][2 + j] = u1;
                sq6[2 * nt + j] = u0 * u0 + u1 * u1;
                du6[2 * nt + j] = xn0 * u0 + xn1 * u1;
            }
        }
#pragma unroll
        for (int o = 4; o <= 16; o <<= 1)
#pragma unroll
            for (int q = 0; q < 6; q++) {
                sq6[q] += __shfl_xor_sync(0xffffffffu, sq6[q], o);
                du6[q] += __shfl_xor_sync(0xffffffffu, du6[q], o);
            }
        if (lane < 4) {
#pragma unroll
            for (int q = 0; q < 6; q++) {
                const int k = 8 * (q >> 1) + gc + (q & 1);
                if (k < KK) {
                    ms->red[w][k] = sq6[q];
                    ms->red[w][KK + k] = du6[q];
                }
            }
        }
        __syncthreads();
        if (tid < KK) {
            float sq = 0.f, du = 0.f;
#pragma unroll
            for (int ww = 0; ww < 8; ww++) {
                sq += ms->red[ww][tid];
                du += ms->red[ww][KK + tid];
            }
            ms->tot[tid] = sq;
            ms->tot[KK + tid] = du;
            asm volatile("st.shared::cluster.f32 [%0], %1;" :: "r"(peer_rpart + tid * 4), "f"(sq) : "memory");
            asm volatile("st.shared::cluster.f32 [%0], %1;" :: "r"(peer_rpart + (KK + tid) * 4), "f"(du) : "memory");
        }
        CLUSTER_SYNC();
        if (tid < KK) {
            const float sq = ms->tot[tid] + ms->rpart[tid];
            const float du = ms->tot[KK + tid] + ms->rpart[KK + tid];
            const float rinv = rsqrtf(fmaxf(sq, 1e-12f));
            ms->rbuf[tid] = rinv;
            if (hasn)
                ms->gbuf[tid] = 1.f / (1.f + __expf(-(rinv * du + g_xk[((size_t)b * SS + sn) * KK + tid])));
        }
        __syncthreads();

#pragma unroll
        for (int nt = 0; nt < 3; nt++) {
#pragma unroll
            for (int j = 0; j < 2; j++) {
                const int k = 8 * nt + gc + j;
                if (k < KK) {
                    const float rv = ms->rbuf[k];
                    const uint32_t roff = (uint32_t)k * PITCHB;
#pragma unroll
                    for (int rr = 0; rr < 2; rr++) {
                        const float hn = c[nt][2 * rr + j] * rv;
                        const __nv_bfloat16 hh = __float2bfloat16(hn);
                        const __nv_bfloat16 hl = __float2bfloat16(hn - __bfloat162float(hh));
                        const unsigned short hb = __bfloat16_as_ushort(hh);
                        const unsigned short lb = __bfloat16_as_ushort(hl);
                        const uint32_t off = roff + (uint32_t)(rr ? eg1 : eg0) * 2;
                        asm volatile("st.shared.u16 [%0], %1;" :: "r"(smbase + OFF_HHI + off), "h"(hb) : "memory");
                        asm volatile("st.shared.u16 [%0], %1;" :: "r"(smbase + OFF_HLO + off), "h"(lb) : "memory");
                        asm volatile("st.shared::cluster.u16 [%0], %1;" :: "r"(peer_base + OFF_HHI + off), "h"(hb) : "memory");
                        asm volatile("st.shared::cluster.u16 [%0], %1;" :: "r"(peer_base + OFF_HLO + off), "h"(lb) : "memory");
                    }
                }
            }
        }
        CLUSTER_SYNC();
    }

    // ---- emit ----
    {
        const int kh = tid >> 7, el = tid & 127;
        const int eg = (int)rank * 128 + el;
#pragma unroll
        for (int j = 0; j < 10; j++) {
            const int k = kh * 10 + j;
            const unsigned short hb = *(unsigned short*)(smraw + OFF_HHI + k * PITCHB + eg * 2);
            const unsigned short lb = *(unsigned short*)(smraw + OFF_HLO + k * PITCHB + eg * 2);
            out[((size_t)b * KK + k) * DD + eg] =
                __bfloat162float(__ushort_as_bfloat16(hb)) + __bfloat162float(__ushort_as_bfloat16(lb));
        }
    }
    CLUSTER_SYNC();
}

extern "C" void kernel_launch(void* const* d_in, const int* in_sizes, int n_in,
                              void* d_out, int out_size) {
    const float* X = (const float*)d_in[0];
    const int* mask = (const int*)d_in[1];
    const float* keys = (const float*)d_in[2];
    const float* U = (const float*)d_in[3];
    const float* V = (const float*)d_in[4];
    const float* W = (const float*)d_in[5];
    float* out = (float*)d_out;

    cudaFuncSetAttribute(rnn_mma_kernel, cudaFuncAttributeMaxDynamicSharedMemorySize, SMEM_TOT);
    cudaFuncSetAttribute(xw_mma_kernel, cudaFuncAttributeMaxDynamicSharedMemorySize, XW_SMEM_TOT);

    xw_mma_kernel<<<BB * (SS / 64), 256, XW_SMEM_TOT>>>(X, W);
    xk_kernel<<<BB * (SS / 8), 256>>>(X, keys);
    rnn_mma_kernel<<<2 * BB, 256, SMEM_TOT>>>(X, mask, keys, U, V, out);
}

// round 11
// speedup vs baseline: 1.1041x; 1.1041x over previous
#include <cuda_runtime.h>
#include <cuda_bf16.h>
#include <math.h>
#include <stdint.h>

// Problem constants
#define BB 256
#define SS 512
#define KK 20
#define DD 256
#define PITCHB 528   // bytes per bf16 row (264 elems): odd 16B count -> ldmatrix conflict-free
#define KVP 132      // kV table pitch (f32)

// Precomputed scratch (static device globals: allocation-free)
__device__ float g_xw[(size_t)BB * SS * DD];            // xW[b][i][e]   (compact index i)
__device__ float g_xk[(size_t)BB * SS * KK];            // x.keys[b][i][k] (compact index i)
__device__ unsigned short g_slist[(size_t)BB * SS];     // active step indices per batch
__device__ int g_nact[BB];                              // active count per batch

// ================= packed f32x2 helpers (xw kernel) =================
__device__ __forceinline__ unsigned long long f2fma(unsigned long long a,
                                                    unsigned long long b,
                                                    unsigned long long c) {
    unsigned long long d;
    asm("fma.rn.f32x2 %0, %1, %2, %3;" : "=l"(d) : "l"(a), "l"(b), "l"(c));
    return d;
}
__device__ __forceinline__ unsigned long long pk2(float a) {
    unsigned int ai = __float_as_uint(a);
    return (((unsigned long long)ai) << 32) | (unsigned long long)ai;
}
__device__ __forceinline__ void upk2(unsigned long long p, float& lo, float& hi) {
    lo = __uint_as_float((unsigned int)(p & 0xffffffffull));
    hi = __uint_as_float((unsigned int)(p >> 32));
}

// ================= PTX helpers =================
__device__ __forceinline__ uint32_t smem_u32(const void* p) {
    uint32_t a;
    asm("{ .reg .u64 t; cvta.to.shared.u64 t, %1; cvt.u32.u64 %0, t; }" : "=r"(a) : "l"(p));
    return a;
}
__device__ __forceinline__ uint32_t cluster_rank() {
    uint32_t r;
    asm("mov.u32 %0, %%cluster_ctarank;" : "=r"(r));
    return r;
}
#define CLUSTER_SYNC() do { \
    asm volatile("barrier.cluster.arrive.aligned;" ::: "memory"); \
    asm volatile("barrier.cluster.wait.aligned;" ::: "memory"); \
} while (0)

#define LDSM4(r, addr) \
    asm volatile("ldmatrix.sync.aligned.m8n8.x4.shared.b16 {%0,%1,%2,%3}, [%4];" \
        : "=r"((r)[0]), "=r"((r)[1]), "=r"((r)[2]), "=r"((r)[3]) : "r"(addr))
#define LDSM2(r, addr) \
    asm volatile("ldmatrix.sync.aligned.m8n8.x2.shared.b16 {%0,%1}, [%2];" \
        : "=r"((r)[0]), "=r"((r)[1]) : "r"(addr))

#define MMA16816(c, a, b0, b1) \
    asm volatile("mma.sync.aligned.m16n8k16.row.col.f32.bf16.bf16.f32 " \
        "{%0,%1,%2,%3}, {%4,%5,%6,%7}, {%8,%9}, {%0,%1,%2,%3};" \
        : "+f"((c)[0]), "+f"((c)[1]), "+f"((c)[2]), "+f"((c)[3]) \
        : "r"((a)[0]), "r"((a)[1]), "r"((a)[2]), "r"((a)[3]), "r"(b0), "r"(b1))

// ================= shared memory layout (rnn kernel) =================
struct MiscS {
    float red[8][2 * KK];
    float tot[2 * KK];
    float rpart[2 * KK];
    float gbuf[KK];
    float rbuf[KK];
    unsigned short slist[SS];
    int wcnt[8];
};
#define OFF_ULO 0                                 // U^T lo [128 e][256 d] bf16 (staged hi first)
#define OFF_HHI (128 * PITCHB)                    // h hi tile [24 k][256 d] bf16
#define OFF_HLO (OFF_HHI + 24 * PITCHB)
#define OFF_KV  (OFF_HLO + 24 * PITCHB)           // kV [20][KVP] f32
#define OFF_MISC (OFF_KV + KK * KVP * 4)
#define SMEM_TOT ((int)(OFF_MISC + sizeof(MiscS)))

// ================= kernel 0: mask compaction to global =================
__global__ void __launch_bounds__(256) mask_kernel(const int* __restrict__ mask) {
    __shared__ int wcnt[8];
    const int b = blockIdx.x;
    const int tid = threadIdx.x;
    const int lane = tid & 31, w = tid >> 5;

    int total = 0;
    for (int r = 0; r < 2; r++) {
        const int idx = r * 256 + tid;
        const int m = (mask[b * SS + idx] != 0);
        const unsigned bal = __ballot_sync(0xffffffffu, m);
        const int pre = __popc(bal & ((1u << lane) - 1));
        if (lane == 0) wcnt[w] = __popc(bal);
        __syncthreads();
        int woff = 0;
        for (int ww = 0; ww < w; ww++) woff += wcnt[ww];
        if (m) g_slist[(size_t)b * SS + total + woff + pre] = (unsigned short)idx;
        int rt = 0;
#pragma unroll
        for (int ww = 0; ww < 8; ww++) rt += wcnt[ww];
        total += rt;
        __syncthreads();
    }
    if (tid == 0) g_nact[b] = total;
}

// ================= kernel 1: xW for ACTIVE steps only (f32x2, proven) =================
__global__ void __launch_bounds__(256) xw_kernel(const float* __restrict__ X,
                                                 const float* __restrict__ W) {
    __shared__ float xt[DD][34];
    __shared__ unsigned short sl[32];
    const int cta = blockIdx.x;
    const int b = cta >> 4;
    const int s0 = (cta & 15) * 32;     // compact row base
    const int tid = threadIdx.x;

    const int n_act = g_nact[b];
    if (s0 >= n_act) return;

    if (tid < 32)
        sl[tid] = (s0 + tid < n_act) ? g_slist[(size_t)b * SS + s0 + tid] : (unsigned short)0;
    __syncthreads();

    for (int idx = tid; idx < 32 * DD; idx += 256) {
        const int ss = idx >> 8, d = idx & 255;
        xt[d][ss] = X[((size_t)b * SS + sl[ss]) * DD + d];
    }
    __syncthreads();

    unsigned long long acc[16];
#pragma unroll
    for (int i = 0; i < 16; i++) acc[i] = 0ull;

    float ua[4], ub[4], un[4];
#pragma unroll
    for (int j = 0; j < 4; j++) ua[j] = W[j * DD + tid];
#pragma unroll
    for (int j = 0; j < 4; j++) ub[j] = W[(4 + j) * DD + tid];
    for (int db = 0; db < 64; db++) {
        const int dn = db * 4 + 8;
        if (dn < DD) {
#pragma unroll
            for (int j = 0; j < 4; j++) un[j] = W[(dn + j) * DD + tid];
        } else {
#pragma unroll
            for (int j = 0; j < 4; j++) un[j] = 0.f;
        }
#pragma unroll
        for (int dd = 0; dd < 4; dd++) {
            const int d = db * 4 + dd;
            const unsigned long long* xr = (const unsigned long long*)xt[d];
            unsigned long long ww = pk2(ua[dd]);
#pragma unroll
            for (int j = 0; j < 16; j++) acc[j] = f2fma(xr[j], ww, acc[j]);
        }
#pragma unroll
        for (int j = 0; j < 4; j++) { ua[j] = ub[j]; ub[j] = un[j]; }
    }
#pragma unroll
    for (int j = 0; j < 16; j++) {
        float lo, hi;
        upk2(acc[j], lo, hi);
        const int r0 = s0 + 2 * j, r1 = s0 + 2 * j + 1;
        if (r0 < n_act) g_xw[((size_t)b * SS + r0) * DD + tid] = lo;
        if (r1 < n_act) g_xw[((size_t)b * SS + r1) * DD + tid] = hi;
    }
}

// ================= kernel 1b: xk for ACTIVE steps only =================
__global__ void __launch_bounds__(256) xk_kernel(const float* __restrict__ X,
                                                 const float* __restrict__ keys) {
    const int b = blockIdx.x >> 6;
    const int i = ((blockIdx.x & 63) << 3) + (threadIdx.x >> 5);
    const int lane = threadIdx.x & 31;
    if (i >= g_nact[b]) return;    // whole warp shares i
    const int s = g_slist[(size_t)b * SS + i];
    const float* x = X + ((size_t)b * SS + s) * DD;
    const float* kb = keys + (size_t)b * KK * DD;

    float xr[8];
#pragma unroll
    for (int c = 0; c < 8; c++) xr[c] = x[lane + 32 * c];

    float pk[KK];
#pragma unroll
    for (int k = 0; k < KK; k++) {
        float p = 0.f;
#pragma unroll
        for (int c = 0; c < 8; c++) p = fmaf(xr[c], kb[k * DD + lane + 32 * c], p);
        pk[k] = p;
    }
#pragma unroll
    for (int o = 16; o; o >>= 1)
#pragma unroll
        for (int k = 0; k < KK; k++) pk[k] += __shfl_xor_sync(0xffffffffu, pk[k], o);

    if (lane < KK)
        g_xk[((size_t)b * SS + i) * KK + lane] = pk[lane];
}

// ================= kernel 2: HMMA recurrent kernel (proven R7 compute) =================
__global__ void __launch_bounds__(256, 2) __cluster_dims__(2, 1, 1)
rnn_mma_kernel(const float* __restrict__ X, const int* __restrict__ mask,
               const float* __restrict__ keys, const float* __restrict__ U,
               const float* __restrict__ V, float* __restrict__ out) {
    extern __shared__ __align__(16) unsigned char smraw[];
    MiscS* ms = (MiscS*)(smraw + OFF_MISC);
    float* kVs = (float*)(smraw + OFF_KV);

    const int tid = threadIdx.x;
    const int lane = tid & 31, w = tid >> 5;
    const int b = blockIdx.x >> 1;
    const uint32_t rank = cluster_rank();
    const uint32_t smbase = smem_u32(smraw);

    const int e0 = w * 16;
    const int gr = lane >> 2;
    const int gc = (lane & 3) * 2;
    const int el0 = e0 + gr;
    const int el1 = e0 + 8 + gr;
    const int eg0 = (int)rank * 128 + el0;
    const int eg1 = (int)rank * 128 + el1;

    // ---- load precomputed active list ----
    const int n_act = g_nact[b];
    for (int idx = tid; idx < SS; idx += 256)
        ms->slist[idx] = g_slist[(size_t)b * SS + idx];

    // ---- stage U^T HI, preload A frags, overwrite with LO ----
    for (int idx = tid; idx < 128 * DD; idx += 256) {
        const int el = idx & 127, d = idx >> 7;
        const float f = U[(size_t)d * DD + rank * 128 + el];
        *(unsigned short*)(smraw + OFF_ULO + el * PITCHB + d * 2) =
            __bfloat16_as_ushort(__float2bfloat16(f));
    }
    __syncthreads();

    const uint32_t aoff = (uint32_t)(e0 + (lane & 7) + ((lane >> 3) & 1) * 8) * PITCHB
                        + (uint32_t)((lane >> 4) & 1) * 16;
    uint32_t uh[16][4];
#pragma unroll
    for (int kc = 0; kc < 16; kc++)
        LDSM4(uh[kc], smbase + OFF_ULO + aoff + (uint32_t)kc * 32);
    __syncthreads();

    for (int idx = tid; idx < 128 * DD; idx += 256) {
        const int el = idx & 127, d = idx >> 7;
        const float f = U[(size_t)d * DD + rank * 128 + el];
        const __nv_bfloat16 hi = __float2bfloat16(f);
        *(unsigned short*)(smraw + OFF_ULO + el * PITCHB + d * 2) =
            __bfloat16_as_ushort(__float2bfloat16(f - __bfloat162float(hi)));
    }

    // zero h tiles
    {
        const uint4 z = make_uint4(0, 0, 0, 0);
        uint4* p = (uint4*)(smraw + OFF_HHI);
        for (int i = tid; i < (2 * 24 * PITCHB) / 16; i += 256) p[i] = z;
    }

    // kV table
    {
        const int kh = tid >> 7, el = tid & 127;
        float kvv[10];
#pragma unroll
        for (int j = 0; j < 10; j++) kvv[j] = 0.f;
        const float* kr = keys + (size_t)b * KK * DD + (size_t)kh * 10 * DD;
#pragma unroll 4
        for (int d = 0; d < DD; d++) {
            const float vv = V[(size_t)d * DD + rank * 128 + el];
#pragma unroll
            for (int j = 0; j < 10; j++) kvv[j] = fmaf(kr[j * DD + d], vv, kvv[j]);
        }
#pragma unroll
        for (int j = 0; j < 10; j++) kVs[(kh * 10 + j) * KVP + el] = kvv[j];
    }

    if (tid < KK && n_act > 0)
        ms->gbuf[tid] = 1.f / (1.f + __expf(-g_xk[((size_t)b * SS + 0) * KK + tid]));
    __syncthreads();
    CLUSTER_SYNC();

    uint32_t peer_base;
    asm("mapa.shared::cluster.u32 %0, %1, %2;" : "=r"(peer_base) : "r"(smbase), "r"(rank ^ 1u));
    const uint32_t peer_rpart = peer_base + OFF_MISC + (uint32_t)offsetof(MiscS, rpart);

    const uint32_t bOff4 = (uint32_t)(8 * ((lane >> 4) & 1) + (lane & 7)) * PITCHB
                         + (uint32_t)((lane >> 3) & 1) * 16;
    const uint32_t bOff2 = (uint32_t)(16 + (lane & 7)) * PITCHB
                         + (uint32_t)((lane >> 3) & 1) * 16;
    const uint32_t hhi = smbase + OFF_HHI, hlo = smbase + OFF_HLO;
    const uint32_t ulo = smbase + OFF_ULO;

    for (int i = 0; i < n_act; i++) {
        const bool hasn = (i + 1 < n_act);
        const int sn = hasn ? (int)ms->slist[i + 1] : 0;
        const float xw0 = g_xw[((size_t)b * SS + i) * DD + eg0];
        const float xw1 = g_xw[((size_t)b * SS + i) * DD + eg1];
        float xn0 = 0.f, xn1 = 0.f;
        if (hasn) {
            xn0 = X[((size_t)b * SS + sn) * DD + eg0];
            xn1 = X[((size_t)b * SS + sn) * DD + eg1];
        }

        float c[3][4];
#pragma unroll
        for (int nt = 0; nt < 3; nt++)
#pragma unroll
            for (int q = 0; q < 4; q++) c[nt][q] = 0.f;

#pragma unroll
        for (int kc = 0; kc < 16; kc++) {
            const uint32_t dofs = (uint32_t)kc * 32;
            uint32_t bh[4], b2[2], al[4], bl[4], bl2[2];
            LDSM4(bh, hhi + bOff4 + dofs);
            LDSM2(b2, hhi + bOff2 + dofs);
            LDSM4(al, ulo + aoff + dofs);
            MMA16816(c[0], uh[kc], bh[0], bh[1]);
            MMA16816(c[1], uh[kc], bh[2], bh[3]);
            MMA16816(c[2], uh[kc], b2[0], b2[1]);
            MMA16816(c[0], al, bh[0], bh[1]);
            MMA16816(c[1], al, bh[2], bh[3]);
            MMA16816(c[2], al, b2[0], b2[1]);
            LDSM4(bl, hlo + bOff4 + dofs);
            LDSM2(bl2, hlo + bOff2 + dofs);
            MMA16816(c[0], uh[kc], bl[0], bl[1]);
            MMA16816(c[1], uh[kc], bl[2], bl[3]);
            MMA16816(c[2], uh[kc], bl2[0], bl2[1]);
        }

        float sq6[6], du6[6];
#pragma unroll
        for (int nt = 0; nt < 3; nt++) {
#pragma unroll
            for (int j = 0; j < 2; j++) {
                const int k = 8 * nt + gc + j;
                const bool val = (k < KK);
                const int kk = val ? k : 0;
                const float gv = val ? ms->gbuf[kk] : 0.f;
                const float kv0 = kVs[kk * KVP + el0];
                const float kv1 = kVs[kk * KVP + el1];
                float u0 = 0.f, u1 = 0.f;
                if (val) {
                    const unsigned short h0h = *(unsigned short*)(smraw + OFF_HHI + kk * PITCHB + eg0 * 2);
                    const unsigned short h0l = *(unsigned short*)(smraw + OFF_HLO + kk * PITCHB + eg0 * 2);
                    const unsigned short h1h = *(unsigned short*)(smraw + OFF_HHI + kk * PITCHB + eg1 * 2);
                    const unsigned short h1l = *(unsigned short*)(smraw + OFF_HLO + kk * PITCHB + eg1 * 2);
                    const float ho0 = __bfloat162float(__ushort_as_bfloat16(h0h)) +
                                      __bfloat162float(__ushort_as_bfloat16(h0l));
                    const float ho1 = __bfloat162float(__ushort_as_bfloat16(h1h)) +
                                      __bfloat162float(__ushort_as_bfloat16(h1l));
                    u0 = ho0 + gv * fmaxf(c[nt][j] + kv0 + xw0, 0.f);
                    u1 = ho1 + gv * fmaxf(c[nt][2 + j] + kv1 + xw1, 0.f);
                }
                c[nt][j] = u0;
                c[nt][2 + j] = u1;
                sq6[2 * nt + j] = u0 * u0 + u1 * u1;
                du6[2 * nt + j] = xn0 * u0 + xn1 * u1;
            }
        }
#pragma unroll
        for (int o = 4; o <= 16; o <<= 1)
#pragma unroll
            for (int q = 0; q < 6; q++) {
                sq6[q] += __shfl_xor_sync(0xffffffffu, sq6[q], o);
                du6[q] += __shfl_xor_sync(0xffffffffu, du6[q], o);
            }
        if (lane < 4) {
#pragma unroll
            for (int q = 0; q < 6; q++) {
                const int k = 8 * (q >> 1) + gc + (q & 1);
                if (k < KK) {
                    ms->red[w][k] = sq6[q];
                    ms->red[w][KK + k] = du6[q];
                }
            }
        }
        __syncthreads();
        if (tid < KK) {
            float sq = 0.f, du = 0.f;
#pragma unroll
            for (int ww = 0; ww < 8; ww++) {
                sq += ms->red[ww][tid];
                du += ms->red[ww][KK + tid];
            }
            ms->tot[tid] = sq;
            ms->tot[KK + tid] = du;
            asm volatile("st.shared::cluster.f32 [%0], %1;" :: "r"(peer_rpart + tid * 4), "f"(sq) : "memory");
            asm volatile("st.shared::cluster.f32 [%0], %1;" :: "r"(peer_rpart + (KK + tid) * 4), "f"(du) : "memory");
        }
        CLUSTER_SYNC();
        if (tid < KK) {
            const float sq = ms->tot[tid] + ms->rpart[tid];
            const float du = ms->tot[KK + tid] + ms->rpart[KK + tid];
            const float rinv = rsqrtf(fmaxf(sq, 1e-12f));
            ms->rbuf[tid] = rinv;
            if (hasn)
                ms->gbuf[tid] = 1.f / (1.f + __expf(-(rinv * du + g_xk[((size_t)b * SS + i + 1) * KK + tid])));
        }
        __syncthreads();

#pragma unroll
        for (int nt = 0; nt < 3; nt++) {
#pragma unroll
            for (int j = 0; j < 2; j++) {
                const int k = 8 * nt + gc + j;
                if (k < KK) {
                    const float rv = ms->rbuf[k];
                    const uint32_t roff = (uint32_t)k * PITCHB;
#pragma unroll
                    for (int rr = 0; rr < 2; rr++) {
                        const float hn = c[nt][2 * rr + j] * rv;
                        const __nv_bfloat16 hh = __float2bfloat16(hn);
                        const __nv_bfloat16 hl = __float2bfloat16(hn - __bfloat162float(hh));
                        const unsigned short hb = __bfloat16_as_ushort(hh);
                        const unsigned short lb = __bfloat16_as_ushort(hl);
                        const uint32_t off = roff + (uint32_t)(rr ? eg1 : eg0) * 2;
                        asm volatile("st.shared.u16 [%0], %1;" :: "r"(smbase + OFF_HHI + off), "h"(hb) : "memory");
                        asm volatile("st.shared.u16 [%0], %1;" :: "r"(smbase + OFF_HLO + off), "h"(lb) : "memory");
                        asm volatile("st.shared::cluster.u16 [%0], %1;" :: "r"(peer_base + OFF_HHI + off), "h"(hb) : "memory");
                        asm volatile("st.shared::cluster.u16 [%0], %1;" :: "r"(peer_base + OFF_HLO + off), "h"(lb) : "memory");
                    }
                }
            }
        }
        CLUSTER_SYNC();
    }

    // ---- emit ----
    {
        const int kh = tid >> 7, el = tid & 127;
        const int eg = (int)rank * 128 + el;
#pragma unroll
        for (int j = 0; j < 10; j++) {
            const int k = kh * 10 + j;
            const unsigned short hb = *(unsigned short*)(smraw + OFF_HHI + k * PITCHB + eg * 2);
            const unsigned short lb = *(unsigned short*)(smraw + OFF_HLO + k * PITCHB + eg * 2);
            out[((size_t)b * KK + k) * DD + eg] =
                __bfloat162float(__ushort_as_bfloat16(hb)) + __bfloat162float(__ushort_as_bfloat16(lb));
        }
    }
    CLUSTER_SYNC();
}

extern "C" void kernel_launch(void* const* d_in, const int* in_sizes, int n_in,
                              void* d_out, int out_size) {
    const float* X = (const float*)d_in[0];
    const int* mask = (const int*)d_in[1];
    const float* keys = (const float*)d_in[2];
    const float* U = (const float*)d_in[3];
    const float* V = (const float*)d_in[4];
    const float* W = (const float*)d_in[5];
    float* out = (float*)d_out;

    cudaFuncSetAttribute(rnn_mma_kernel, cudaFuncAttributeMaxDynamicSharedMemorySize, SMEM_TOT);

    mask_kernel<<<BB, 256>>>(mask);
    xw_kernel<<<BB * (SS / 32), 256>>>(X, W);
    xk_kernel<<<BB * (SS / 8), 256>>>(X, keys);
    rnn_mma_kernel<<<2 * BB, 256, SMEM_TOT>>>(X, mask, keys, U, V, out);
}

// round 12
// speedup vs baseline: 1.1763x; 1.0654x over previous
#include <cuda_runtime.h>
#include <cuda_bf16.h>
#include <math.h>
#include <stdint.h>

// Problem constants
#define BB 256
#define SS 512
#define KK 20
#define DD 256
#define PITCHB 528   // bytes per bf16 row (264 elems): odd 16B count -> ldmatrix conflict-free
#define KVP 132      // kV table pitch (f32)

// Precomputed scratch (static device globals: allocation-free)
__device__ float g_xw[(size_t)BB * SS * DD];            // xW[b][i][e]   (compact index i)
__device__ float g_xk[(size_t)BB * SS * KK];            // x.keys[b][i][k] (compact index i)
__device__ unsigned short g_slist[(size_t)BB * SS];     // active step indices per batch
__device__ int g_nact[BB];                              // active count per batch

// ================= packed f32x2 helpers (xw kernel) =================
__device__ __forceinline__ unsigned long long f2fma(unsigned long long a,
                                                    unsigned long long b,
                                                    unsigned long long c) {
    unsigned long long d;
    asm("fma.rn.f32x2 %0, %1, %2, %3;" : "=l"(d) : "l"(a), "l"(b), "l"(c));
    return d;
}
__device__ __forceinline__ unsigned long long pk2(float a) {
    unsigned int ai = __float_as_uint(a);
    return (((unsigned long long)ai) << 32) | (unsigned long long)ai;
}
__device__ __forceinline__ void upk2(unsigned long long p, float& lo, float& hi) {
    lo = __uint_as_float((unsigned int)(p & 0xffffffffull));
    hi = __uint_as_float((unsigned int)(p >> 32));
}

// ================= PTX helpers =================
__device__ __forceinline__ uint32_t smem_u32(const void* p) {
    uint32_t a;
    asm("{ .reg .u64 t; cvta.to.shared.u64 t, %1; cvt.u32.u64 %0, t; }" : "=r"(a) : "l"(p));
    return a;
}
__device__ __forceinline__ uint32_t cluster_rank() {
    uint32_t r;
    asm("mov.u32 %0, %%cluster_ctarank;" : "=r"(r));
    return r;
}
#define CLUSTER_SYNC() do { \
    asm volatile("barrier.cluster.arrive.aligned;" ::: "memory"); \
    asm volatile("barrier.cluster.wait.aligned;" ::: "memory"); \
} while (0)

#define MBARRIER_INIT(addr, cnt) \
    asm volatile("mbarrier.init.shared.b64 [%0], %1;" :: "r"((uint32_t)(addr)), "r"((uint32_t)(cnt)) : "memory")

// arrive on a PEER CTA's mbarrier (remote DSMEM address), release at cluster scope
#define MBAR_ARRIVE_REMOTE(remaddr) \
    asm volatile("mbarrier.arrive.release.cluster.shared::cluster.b64 _, [%0];" \
        :: "r"((uint32_t)(remaddr)) : "memory")

// wait on LOCAL mbarrier with acquire at cluster scope (observes peer's released stores)
#define MBAR_WAIT_CL(addr, par) do { \
    uint32_t _m = (uint32_t)(addr), _p = (uint32_t)(par), _d; \
    asm volatile("{ .reg .pred p; mbarrier.try_wait.parity.acquire.cluster.shared::cta.b64 p, [%1], %2; selp.b32 %0, 1, 0, p; }" \
        : "=r"(_d) : "r"(_m), "r"(_p) : "memory"); \
    if (!_d) { \
        asm volatile("{ .reg .pred P1;\nWAIT_LOOP_%=:\n" \
            "mbarrier.try_wait.parity.acquire.cluster.shared::cta.b64 P1, [%0], %1, 0x989680;\n" \
            "@P1 bra.uni WAIT_DONE_%=;\nbra.uni WAIT_LOOP_%=;\nWAIT_DONE_%=:\n}" \
            :: "r"(_m), "r"(_p) : "memory"); \
    } \
} while (0)

#define LDSM4(r, addr) \
    asm volatile("ldmatrix.sync.aligned.m8n8.x4.shared.b16 {%0,%1,%2,%3}, [%4];" \
        : "=r"((r)[0]), "=r"((r)[1]), "=r"((r)[2]), "=r"((r)[3]) : "r"(addr))
#define LDSM2(r, addr) \
    asm volatile("ldmatrix.sync.aligned.m8n8.x2.shared.b16 {%0,%1}, [%2];" \
        : "=r"((r)[0]), "=r"((r)[1]) : "r"(addr))

#define MMA16816(c, a, b0, b1) \
    asm volatile("mma.sync.aligned.m16n8k16.row.col.f32.bf16.bf16.f32 " \
        "{%0,%1,%2,%3}, {%4,%5,%6,%7}, {%8,%9}, {%0,%1,%2,%3};" \
        : "+f"((c)[0]), "+f"((c)[1]), "+f"((c)[2]), "+f"((c)[3]) \
        : "r"((a)[0]), "r"((a)[1]), "r"((a)[2]), "r"((a)[3]), "r"(b0), "r"(b1))

// ================= shared memory layout (rnn kernel) =================
struct MiscS {
    unsigned long long mbar0;  // partials-exchanged barrier (count 20)
    unsigned long long mbar1;  // h-tiles-written barrier (count 256)
    float red[8][2 * KK];
    float tot[2 * KK];
    float rpart[2 * KK];
    float gbuf[KK];
    float rbuf[KK];
    unsigned short slist[SS];
};
#define OFF_ULO 0                                 // U^T lo [128 e][256 d] bf16 (staged hi first)
#define OFF_HHI (128 * PITCHB)                    // h hi tile [24 k][256 d] bf16
#define OFF_HLO (OFF_HHI + 24 * PITCHB)
#define OFF_KV  (OFF_HLO + 24 * PITCHB)           // kV [20][KVP] f32
#define OFF_MISC (OFF_KV + KK * KVP * 4)
#define SMEM_TOT ((int)(OFF_MISC + sizeof(MiscS)))

// ================= kernel 0: mask compaction to global =================
__global__ void __launch_bounds__(256) mask_kernel(const int* __restrict__ mask) {
    __shared__ int wcnt[8];
    const int b = blockIdx.x;
    const int tid = threadIdx.x;
    const int lane = tid & 31, w = tid >> 5;

    int total = 0;
    for (int r = 0; r < 2; r++) {
        const int idx = r * 256 + tid;
        const int m = (mask[b * SS + idx] != 0);
        const unsigned bal = __ballot_sync(0xffffffffu, m);
        const int pre = __popc(bal & ((1u << lane) - 1));
        if (lane == 0) wcnt[w] = __popc(bal);
        __syncthreads();
        int woff = 0;
        for (int ww = 0; ww < w; ww++) woff += wcnt[ww];
        if (m) g_slist[(size_t)b * SS + total + woff + pre] = (unsigned short)idx;
        int rt = 0;
#pragma unroll
        for (int ww = 0; ww < 8; ww++) rt += wcnt[ww];
        total += rt;
        __syncthreads();
    }
    if (tid == 0) g_nact[b] = total;
}

// ================= kernel 1: xW for ACTIVE steps only (f32x2, proven) =================
__global__ void __launch_bounds__(256) xw_kernel(const float* __restrict__ X,
                                                 const float* __restrict__ W) {
    __shared__ float xt[DD][34];
    __shared__ unsigned short sl[32];
    const int cta = blockIdx.x;
    const int b = cta >> 4;
    const int s0 = (cta & 15) * 32;     // compact row base
    const int tid = threadIdx.x;

    const int n_act = g_nact[b];
    if (s0 >= n_act) return;

    if (tid < 32)
        sl[tid] = (s0 + tid < n_act) ? g_slist[(size_t)b * SS + s0 + tid] : (unsigned short)0;
    __syncthreads();

    for (int idx = tid; idx < 32 * DD; idx += 256) {
        const int ss = idx >> 8, d = idx & 255;
        xt[d][ss] = X[((size_t)b * SS + sl[ss]) * DD + d];
    }
    __syncthreads();

    unsigned long long acc[16];
#pragma unroll
    for (int i = 0; i < 16; i++) acc[i] = 0ull;

    float ua[4], ub[4], un[4];
#pragma unroll
    for (int j = 0; j < 4; j++) ua[j] = W[j * DD + tid];
#pragma unroll
    for (int j = 0; j < 4; j++) ub[j] = W[(4 + j) * DD + tid];
    for (int db = 0; db < 64; db++) {
        const int dn = db * 4 + 8;
        if (dn < DD) {
#pragma unroll
            for (int j = 0; j < 4; j++) un[j] = W[(dn + j) * DD + tid];
        } else {
#pragma unroll
            for (int j = 0; j < 4; j++) un[j] = 0.f;
        }
#pragma unroll
        for (int dd = 0; dd < 4; dd++) {
            const int d = db * 4 + dd;
            const unsigned long long* xr = (const unsigned long long*)xt[d];
            unsigned long long ww = pk2(ua[dd]);
#pragma unroll
            for (int j = 0; j < 16; j++) acc[j] = f2fma(xr[j], ww, acc[j]);
        }
#pragma unroll
        for (int j = 0; j < 4; j++) { ua[j] = ub[j]; ub[j] = un[j]; }
    }
#pragma unroll
    for (int j = 0; j < 16; j++) {
        float lo, hi;
        upk2(acc[j], lo, hi);
        const int r0 = s0 + 2 * j, r1 = s0 + 2 * j + 1;
        if (r0 < n_act) g_xw[((size_t)b * SS + r0) * DD + tid] = lo;
        if (r1 < n_act) g_xw[((size_t)b * SS + r1) * DD + tid] = hi;
    }
}

// ================= kernel 1b: xk for ACTIVE steps only =================
__global__ void __launch_bounds__(256) xk_kernel(const float* __restrict__ X,
                                                 const float* __restrict__ keys) {
    const int b = blockIdx.x >> 6;
    const int i = ((blockIdx.x & 63) << 3) + (threadIdx.x >> 5);
    const int lane = threadIdx.x & 31;
    if (i >= g_nact[b]) return;    // whole warp shares i
    const int s = g_slist[(size_t)b * SS + i];
    const float* x = X + ((size_t)b * SS + s) * DD;
    const float* kb = keys + (size_t)b * KK * DD;

    float xr[8];
#pragma unroll
    for (int c = 0; c < 8; c++) xr[c] = x[lane + 32 * c];

    float pk[KK];
#pragma unroll
    for (int k = 0; k < KK; k++) {
        float p = 0.f;
#pragma unroll
        for (int c = 0; c < 8; c++) p = fmaf(xr[c], kb[k * DD + lane + 32 * c], p);
        pk[k] = p;
    }
#pragma unroll
    for (int o = 16; o; o >>= 1)
#pragma unroll
        for (int k = 0; k < KK; k++) pk[k] += __shfl_xor_sync(0xffffffffu, pk[k], o);

    if (lane < KK)
        g_xk[((size_t)b * SS + i) * KK + lane] = pk[lane];
}

// ================= kernel 2: HMMA recurrent kernel (mbarrier handshake) =================
__global__ void __launch_bounds__(256, 2) __cluster_dims__(2, 1, 1)
rnn_mma_kernel(const float* __restrict__ X, const int* __restrict__ mask,
               const float* __restrict__ keys, const float* __restrict__ U,
               const float* __restrict__ V, float* __restrict__ out) {
    extern __shared__ __align__(16) unsigned char smraw[];
    MiscS* ms = (MiscS*)(smraw + OFF_MISC);
    float* kVs = (float*)(smraw + OFF_KV);

    const int tid = threadIdx.x;
    const int lane = tid & 31, w = tid >> 5;
    const int b = blockIdx.x >> 1;
    const uint32_t rank = cluster_rank();
    const uint32_t smbase = smem_u32(smraw);

    const int e0 = w * 16;
    const int gr = lane >> 2;
    const int gc = (lane & 3) * 2;
    const int el0 = e0 + gr;
    const int el1 = e0 + 8 + gr;
    const int eg0 = (int)rank * 128 + el0;
    const int eg1 = (int)rank * 128 + el1;

    // ---- load precomputed active list + init mbarriers ----
    const int n_act = g_nact[b];
    for (int idx = tid; idx < SS; idx += 256)
        ms->slist[idx] = g_slist[(size_t)b * SS + idx];
    if (tid == 0) {
        MBARRIER_INIT(smem_u32(&ms->mbar0), KK);    // 20 partial-arrivals per step
        MBARRIER_INIT(smem_u32(&ms->mbar1), 256);   // 256 h-arrivals per step
    }

    // ---- stage U^T HI, preload A frags, overwrite with LO ----
    for (int idx = tid; idx < 128 * DD; idx += 256) {
        const int el = idx & 127, d = idx >> 7;
        const float f = U[(size_t)d * DD + rank * 128 + el];
        *(unsigned short*)(smraw + OFF_ULO + el * PITCHB + d * 2) =
            __bfloat16_as_ushort(__float2bfloat16(f));
    }
    __syncthreads();

    const uint32_t aoff = (uint32_t)(e0 + (lane & 7) + ((lane >> 3) & 1) * 8) * PITCHB
                        + (uint32_t)((lane >> 4) & 1) * 16;
    uint32_t uh[16][4];
#pragma unroll
    for (int kc = 0; kc < 16; kc++)
        LDSM4(uh[kc], smbase + OFF_ULO + aoff + (uint32_t)kc * 32);
    __syncthreads();

    for (int idx = tid; idx < 128 * DD; idx += 256) {
        const int el = idx & 127, d = idx >> 7;
        const float f = U[(size_t)d * DD + rank * 128 + el];
        const __nv_bfloat16 hi = __float2bfloat16(f);
        *(unsigned short*)(smraw + OFF_ULO + el * PITCHB + d * 2) =
            __bfloat16_as_ushort(__float2bfloat16(f - __bfloat162float(hi)));
    }

    // zero h tiles
    {
        const uint4 z = make_uint4(0, 0, 0, 0);
        uint4* p = (uint4*)(smraw + OFF_HHI);
        for (int i = tid; i < (2 * 24 * PITCHB) / 16; i += 256) p[i] = z;
    }

    // kV table
    {
        const int kh = tid >> 7, el = tid & 127;
        float kvv[10];
#pragma unroll
        for (int j = 0; j < 10; j++) kvv[j] = 0.f;
        const float* kr = keys + (size_t)b * KK * DD + (size_t)kh * 10 * DD;
#pragma unroll 4
        for (int d = 0; d < DD; d++) {
            const float vv = V[(size_t)d * DD + rank * 128 + el];
#pragma unroll
            for (int j = 0; j < 10; j++) kvv[j] = fmaf(kr[j * DD + d], vv, kvv[j]);
        }
#pragma unroll
        for (int j = 0; j < 10; j++) kVs[(kh * 10 + j) * KVP + el] = kvv[j];
    }

    if (tid < KK && n_act > 0)
        ms->gbuf[tid] = 1.f / (1.f + __expf(-g_xk[((size_t)b * SS + 0) * KK + tid]));
    __syncthreads();
    CLUSTER_SYNC();   // mbarrier init + tiles visible cluster-wide before any remote traffic

    uint32_t peer_base;
    asm("mapa.shared::cluster.u32 %0, %1, %2;" : "=r"(peer_base) : "r"(smbase), "r"(rank ^ 1u));
    const uint32_t peer_rpart = peer_base + OFF_MISC + (uint32_t)offsetof(MiscS, rpart);
    const uint32_t peer_mbar0 = peer_base + OFF_MISC + (uint32_t)offsetof(MiscS, mbar0);
    const uint32_t peer_mbar1 = peer_base + OFF_MISC + (uint32_t)offsetof(MiscS, mbar1);
    const uint32_t loc_mbar0 = smem_u32(&ms->mbar0);
    const uint32_t loc_mbar1 = smem_u32(&ms->mbar1);

    const uint32_t bOff4 = (uint32_t)(8 * ((lane >> 4) & 1) + (lane & 7)) * PITCHB
                         + (uint32_t)((lane >> 3) & 1) * 16;
    const uint32_t bOff2 = (uint32_t)(16 + (lane & 7)) * PITCHB
                         + (uint32_t)((lane >> 3) & 1) * 16;
    const uint32_t hhi = smbase + OFF_HHI, hlo = smbase + OFF_HLO;
    const uint32_t ulo = smbase + OFF_ULO;

    // h state lives in registers, mirrored in the bf16 smem tiles for the MMA
    float hreg[3][4];
#pragma unroll
    for (int nt = 0; nt < 3; nt++)
#pragma unroll
        for (int q = 0; q < 4; q++) hreg[nt][q] = 0.f;

    int ph = 0;
    for (int i = 0; i < n_act; i++) {
        const bool hasn = (i + 1 < n_act);
        const int sn = hasn ? (int)ms->slist[i + 1] : 0;
        const float xw0 = g_xw[((size_t)b * SS + i) * DD + eg0];
        const float xw1 = g_xw[((size_t)b * SS + i) * DD + eg1];
        float xn0 = 0.f, xn1 = 0.f;
        if (hasn) {
            xn0 = X[((size_t)b * SS + sn) * DD + eg0];
            xn1 = X[((size_t)b * SS + sn) * DD + eg1];
        }

        float c[3][4];
#pragma unroll
        for (int nt = 0; nt < 3; nt++)
#pragma unroll
            for (int q = 0; q < 4; q++) c[nt][q] = 0.f;

#pragma unroll
        for (int kc = 0; kc < 16; kc++) {
            const uint32_t dofs = (uint32_t)kc * 32;
            uint32_t bh[4], b2[2], al[4], bl[4], bl2[2];
            LDSM4(bh, hhi + bOff4 + dofs);
            LDSM2(b2, hhi + bOff2 + dofs);
            LDSM4(al, ulo + aoff + dofs);
            MMA16816(c[0], uh[kc], bh[0], bh[1]);
            MMA16816(c[1], uh[kc], bh[2], bh[3]);
            MMA16816(c[2], uh[kc], b2[0], b2[1]);
            MMA16816(c[0], al, bh[0], bh[1]);
            MMA16816(c[1], al, bh[2], bh[3]);
            MMA16816(c[2], al, b2[0], b2[1]);
            LDSM4(bl, hlo + bOff4 + dofs);
            LDSM2(bl2, hlo + bOff2 + dofs);
            MMA16816(c[0], uh[kc], bl[0], bl[1]);
            MMA16816(c[1], uh[kc], bl[2], bl[3]);
            MMA16816(c[2], uh[kc], bl2[0], bl2[1]);
        }

        float sq6[6], du6[6];
#pragma unroll
        for (int nt = 0; nt < 3; nt++) {
#pragma unroll
            for (int j = 0; j < 2; j++) {
                const int k = 8 * nt + gc + j;
                const bool val = (k < KK);
                const int kk = val ? k : 0;
                const float gv = val ? ms->gbuf[kk] : 0.f;
                const float kv0 = kVs[kk * KVP + el0];
                const float kv1 = kVs[kk * KVP + el1];
                float u0 = 0.f, u1 = 0.f;
                if (val) {
                    u0 = hreg[nt][j] + gv * fmaxf(c[nt][j] + kv0 + xw0, 0.f);
                    u1 = hreg[nt][2 + j] + gv * fmaxf(c[nt][2 + j] + kv1 + xw1, 0.f);
                }
                c[nt][j] = u0;
                c[nt][2 + j] = u1;
                sq6[2 * nt + j] = u0 * u0 + u1 * u1;
                du6[2 * nt + j] = xn0 * u0 + xn1 * u1;
            }
        }
#pragma unroll
        for (int o = 4; o <= 16; o <<= 1)
#pragma unroll
            for (int q = 0; q < 6; q++) {
                sq6[q] += __shfl_xor_sync(0xffffffffu, sq6[q], o);
                du6[q] += __shfl_xor_sync(0xffffffffu, du6[q], o);
            }
        if (lane < 4) {
#pragma unroll
            for (int q = 0; q < 6; q++) {
                const int k = 8 * (q >> 1) + gc + (q & 1);
                if (k < KK) {
                    ms->red[w][k] = sq6[q];
                    ms->red[w][KK + k] = du6[q];
                }
            }
        }
        __syncthreads();
        if (tid < KK) {
            float sq = 0.f, du = 0.f;
#pragma unroll
            for (int ww = 0; ww < 8; ww++) {
                sq += ms->red[ww][tid];
                du += ms->red[ww][KK + tid];
            }
            ms->tot[tid] = sq;
            ms->tot[KK + tid] = du;
            asm volatile("st.shared::cluster.f32 [%0], %1;" :: "r"(peer_rpart + tid * 4), "f"(sq) : "memory");
            asm volatile("st.shared::cluster.f32 [%0], %1;" :: "r"(peer_rpart + (KK + tid) * 4), "f"(du) : "memory");
            MBAR_ARRIVE_REMOTE(peer_mbar0);   // release: covers this thread's two stores
        }
        if (tid < KK) {
            MBAR_WAIT_CL(loc_mbar0, ph);      // peer's 20 partial pairs have landed
            const float sq = ms->tot[tid] + ms->rpart[tid];
            const float du = ms->tot[KK + tid] + ms->rpart[KK + tid];
            const float rinv = rsqrtf(fmaxf(sq, 1e-12f));
            ms->rbuf[tid] = rinv;
            if (hasn)
                ms->gbuf[tid] = 1.f / (1.f + __expf(-(rinv * du + g_xk[((size_t)b * SS + i + 1) * KK + tid])));
        }
        __syncthreads();

        // ---- normalize in regs + write bf16 hi/lo h to local + peer tiles ----
#pragma unroll
        for (int nt = 0; nt < 3; nt++) {
#pragma unroll
            for (int j = 0; j < 2; j++) {
                const int k = 8 * nt + gc + j;
                if (k < KK) {
                    const float rv = ms->rbuf[k];
                    const uint32_t roff = (uint32_t)k * PITCHB;
#pragma unroll
                    for (int rr = 0; rr < 2; rr++) {
                        const float hn = c[nt][2 * rr + j] * rv;
                        hreg[nt][2 * rr + j] = hn;
                        const __nv_bfloat16 hh = __float2bfloat16(hn);
                        const __nv_bfloat16 hl = __float2bfloat16(hn - __bfloat162float(hh));
                        const unsigned short hb = __bfloat16_as_ushort(hh);
                        const unsigned short lb = __bfloat16_as_ushort(hl);
                        const uint32_t off = roff + (uint32_t)(rr ? eg1 : eg0) * 2;
                        asm volatile("st.shared.u16 [%0], %1;" :: "r"(smbase + OFF_HHI + off), "h"(hb) : "memory");
                        asm volatile("st.shared.u16 [%0], %1;" :: "r"(smbase + OFF_HLO + off), "h"(lb) : "memory");
                        asm volatile("st.shared::cluster.u16 [%0], %1;" :: "r"(peer_base + OFF_HHI + off), "h"(hb) : "memory");
                        asm volatile("st.shared::cluster.u16 [%0], %1;" :: "r"(peer_base + OFF_HLO + off), "h"(lb) : "memory");
                    }
                }
            }
        }
        MBAR_ARRIVE_REMOTE(peer_mbar1);       // release: covers this thread's peer-tile stores
        __syncthreads();                      // local tile stores visible CTA-wide
        MBAR_WAIT_CL(loc_mbar1, ph);          // peer's half of our tile has landed
        ph ^= 1;
    }

    // ---- emit straight from registers ----
#pragma unroll
    for (int nt = 0; nt < 3; nt++) {
#pragma unroll
        for (int j = 0; j < 2; j++) {
            const int k = 8 * nt + gc + j;
            if (k < KK) {
                out[((size_t)b * KK + k) * DD + eg0] = hreg[nt][j];
                out[((size_t)b * KK + k) * DD + eg1] = hreg[nt][2 + j];
            }
        }
    }
    CLUSTER_SYNC();   // no CTA exits while peer DSMEM traffic may be in flight
}

extern "C" void kernel_launch(void* const* d_in, const int* in_sizes, int n_in,
                              void* d_out, int out_size) {
    const float* X = (const float*)d_in[0];
    const int* mask = (const int*)d_in[1];
    const float* keys = (const float*)d_in[2];
    const float* U = (const float*)d_in[3];
    const float* V = (const float*)d_in[4];
    const float* W = (const float*)d_in[5];
    float* out = (float*)d_out;

    cudaFuncSetAttribute(rnn_mma_kernel, cudaFuncAttributeMaxDynamicSharedMemorySize, SMEM_TOT);

    mask_kernel<<<BB, 256>>>(mask);
    xw_kernel<<<BB * (SS / 32), 256>>>(X, W);
    xk_kernel<<<BB * (SS / 8), 256>>>(X, keys);
    rnn_mma_kernel<<<2 * BB, 256, SMEM_TOT>>>(X, mask, keys, U, V, out);
}

// round 13
// speedup vs baseline: 1.4330x; 1.2182x over previous
#include <cuda_runtime.h>
#include <cuda_bf16.h>
#include <cuda_fp16.h>
#include <math.h>
#include <stdint.h>

// Problem constants
#define BB 256
#define SS 512
#define KK 20
#define DD 256
#define PITCHB 528   // bytes per fp16 row (264 elems): odd 16B count -> ldmatrix conflict-free
#define KVP 132      // kV table pitch (f32)

// Precomputed scratch (static device globals: allocation-free)
__device__ float g_xw[(size_t)BB * SS * DD];            // xW[b][i][e]   (compact index i)
__device__ float g_xk[(size_t)BB * SS * KK];            // x.keys[b][i][k] (compact index i)
__device__ unsigned short g_slist[(size_t)BB * SS];     // active step indices per batch
__device__ int g_nact[BB];                              // active count per batch

// ================= packed f32x2 helpers (xw kernel) =================
__device__ __forceinline__ unsigned long long f2fma(unsigned long long a,
                                                    unsigned long long b,
                                                    unsigned long long c) {
    unsigned long long d;
    asm("fma.rn.f32x2 %0, %1, %2, %3;" : "=l"(d) : "l"(a), "l"(b), "l"(c));
    return d;
}
__device__ __forceinline__ unsigned long long pk2(float a) {
    unsigned int ai = __float_as_uint(a);
    return (((unsigned long long)ai) << 32) | (unsigned long long)ai;
}
__device__ __forceinline__ void upk2(unsigned long long p, float& lo, float& hi) {
    lo = __uint_as_float((unsigned int)(p & 0xffffffffull));
    hi = __uint_as_float((unsigned int)(p >> 32));
}

// ================= PTX helpers =================
__device__ __forceinline__ uint32_t smem_u32(const void* p) {
    uint32_t a;
    asm("{ .reg .u64 t; cvta.to.shared.u64 t, %1; cvt.u32.u64 %0, t; }" : "=r"(a) : "l"(p));
    return a;
}
__device__ __forceinline__ uint32_t cluster_rank() {
    uint32_t r;
    asm("mov.u32 %0, %%cluster_ctarank;" : "=r"(r));
    return r;
}
#define CLUSTER_SYNC() do { \
    asm volatile("barrier.cluster.arrive.aligned;" ::: "memory"); \
    asm volatile("barrier.cluster.wait.aligned;" ::: "memory"); \
} while (0)

#define MBARRIER_INIT(addr, cnt) \
    asm volatile("mbarrier.init.shared.b64 [%0], %1;" :: "r"((uint32_t)(addr)), "r"((uint32_t)(cnt)) : "memory")

// arrive on a PEER CTA's mbarrier (remote DSMEM address), release at cluster scope
#define MBAR_ARRIVE_REMOTE(remaddr) \
    asm volatile("mbarrier.arrive.release.cluster.shared::cluster.b64 _, [%0];" \
        :: "r"((uint32_t)(remaddr)) : "memory")

// wait on LOCAL mbarrier with acquire at cluster scope (observes peer's released stores)
#define MBAR_WAIT_CL(addr, par) do { \
    uint32_t _m = (uint32_t)(addr), _p = (uint32_t)(par), _d; \
    asm volatile("{ .reg .pred p; mbarrier.try_wait.parity.acquire.cluster.shared::cta.b64 p, [%1], %2; selp.b32 %0, 1, 0, p; }" \
        : "=r"(_d) : "r"(_m), "r"(_p) : "memory"); \
    if (!_d) { \
        asm volatile("{ .reg .pred P1;\nWAIT_LOOP_%=:\n" \
            "mbarrier.try_wait.parity.acquire.cluster.shared::cta.b64 P1, [%0], %1, 0x989680;\n" \
            "@P1 bra.uni WAIT_DONE_%=;\nbra.uni WAIT_LOOP_%=;\nWAIT_DONE_%=:\n}" \
            :: "r"(_m), "r"(_p) : "memory"); \
    } \
} while (0)

#define LDSM4(r, addr) \
    asm volatile("ldmatrix.sync.aligned.m8n8.x4.shared.b16 {%0,%1,%2,%3}, [%4];" \
        : "=r"((r)[0]), "=r"((r)[1]), "=r"((r)[2]), "=r"((r)[3]) : "r"(addr))
#define LDSM2(r, addr) \
    asm volatile("ldmatrix.sync.aligned.m8n8.x2.shared.b16 {%0,%1}, [%2];" \
        : "=r"((r)[0]), "=r"((r)[1]) : "r"(addr))

// fp16 MMA: m16n8k16, f32 accumulate
#define MMA16816(c, a, b0, b1) \
    asm volatile("mma.sync.aligned.m16n8k16.row.col.f32.f16.f16.f32 " \
        "{%0,%1,%2,%3}, {%4,%5,%6,%7}, {%8,%9}, {%0,%1,%2,%3};" \
        : "+f"((c)[0]), "+f"((c)[1]), "+f"((c)[2]), "+f"((c)[3]) \
        : "r"((a)[0]), "r"((a)[1]), "r"((a)[2]), "r"((a)[3]), "r"(b0), "r"(b1))

// ================= shared memory layout (rnn kernel) =================
struct MiscS {
    unsigned long long mbar0;  // partials-exchanged barrier (count 20)
    unsigned long long mbar1;  // h-tiles-written barrier (count 256)
    float red[8][2 * KK];
    float tot[2 * KK];
    float rpart[2 * KK];
    float gbuf[KK];
    float rbuf[KK];
    unsigned short slist[SS];
};
#define OFF_ULO 0                                 // U^T lo fp16 [128 e][256 d] (staged hi first)
#define OFF_HHI (128 * PITCHB)                    // h hi tile fp16 [24 k][256 d]
#define OFF_KV  (OFF_HHI + 24 * PITCHB)           // kV [20][KVP] f32
#define OFF_MISC (OFF_KV + KK * KVP * 4)
#define SMEM_TOT ((int)(OFF_MISC + sizeof(MiscS)))

// ================= kernel 0: mask compaction to global =================
__global__ void __launch_bounds__(256) mask_kernel(const int* __restrict__ mask) {
    __shared__ int wcnt[8];
    const int b = blockIdx.x;
    const int tid = threadIdx.x;
    const int lane = tid & 31, w = tid >> 5;

    int total = 0;
    for (int r = 0; r < 2; r++) {
        const int idx = r * 256 + tid;
        const int m = (mask[b * SS + idx] != 0);
        const unsigned bal = __ballot_sync(0xffffffffu, m);
        const int pre = __popc(bal & ((1u << lane) - 1));
        if (lane == 0) wcnt[w] = __popc(bal);
        __syncthreads();
        int woff = 0;
        for (int ww = 0; ww < w; ww++) woff += wcnt[ww];
        if (m) g_slist[(size_t)b * SS + total + woff + pre] = (unsigned short)idx;
        int rt = 0;
#pragma unroll
        for (int ww = 0; ww < 8; ww++) rt += wcnt[ww];
        total += rt;
        __syncthreads();
    }
    if (tid == 0) g_nact[b] = total;
}

// ================= kernel 1: xW for ACTIVE steps only (f32x2, proven) =================
__global__ void __launch_bounds__(256) xw_kernel(const float* __restrict__ X,
                                                 const float* __restrict__ W) {
    __shared__ float xt[DD][34];
    __shared__ unsigned short sl[32];
    const int cta = blockIdx.x;
    const int b = cta >> 4;
    const int s0 = (cta & 15) * 32;     // compact row base
    const int tid = threadIdx.x;

    const int n_act = g_nact[b];
    if (s0 >= n_act) return;

    if (tid < 32)
        sl[tid] = (s0 + tid < n_act) ? g_slist[(size_t)b * SS + s0 + tid] : (unsigned short)0;
    __syncthreads();

    for (int idx = tid; idx < 32 * DD; idx += 256) {
        const int ss = idx >> 8, d = idx & 255;
        xt[d][ss] = X[((size_t)b * SS + sl[ss]) * DD + d];
    }
    __syncthreads();

    unsigned long long acc[16];
#pragma unroll
    for (int i = 0; i < 16; i++) acc[i] = 0ull;

    float ua[4], ub[4], un[4];
#pragma unroll
    for (int j = 0; j < 4; j++) ua[j] = W[j * DD + tid];
#pragma unroll
    for (int j = 0; j < 4; j++) ub[j] = W[(4 + j) * DD + tid];
    for (int db = 0; db < 64; db++) {
        const int dn = db * 4 + 8;
        if (dn < DD) {
#pragma unroll
            for (int j = 0; j < 4; j++) un[j] = W[(dn + j) * DD + tid];
        } else {
#pragma unroll
            for (int j = 0; j < 4; j++) un[j] = 0.f;
        }
#pragma unroll
        for (int dd = 0; dd < 4; dd++) {
            const int d = db * 4 + dd;
            const unsigned long long* xr = (const unsigned long long*)xt[d];
            unsigned long long ww = pk2(ua[dd]);
#pragma unroll
            for (int j = 0; j < 16; j++) acc[j] = f2fma(xr[j], ww, acc[j]);
        }
#pragma unroll
        for (int j = 0; j < 4; j++) { ua[j] = ub[j]; ub[j] = un[j]; }
    }
#pragma unroll
    for (int j = 0; j < 16; j++) {
        float lo, hi;
        upk2(acc[j], lo, hi);
        const int r0 = s0 + 2 * j, r1 = s0 + 2 * j + 1;
        if (r0 < n_act) g_xw[((size_t)b * SS + r0) * DD + tid] = lo;
        if (r1 < n_act) g_xw[((size_t)b * SS + r1) * DD + tid] = hi;
    }
}

// ================= kernel 1b: xk for ACTIVE steps only =================
__global__ void __launch_bounds__(256) xk_kernel(const float* __restrict__ X,
                                                 const float* __restrict__ keys) {
    const int b = blockIdx.x >> 6;
    const int i = ((blockIdx.x & 63) << 3) + (threadIdx.x >> 5);
    const int lane = threadIdx.x & 31;
    if (i >= g_nact[b]) return;    // whole warp shares i
    const int s = g_slist[(size_t)b * SS + i];
    const float* x = X + ((size_t)b * SS + s) * DD;
    const float* kb = keys + (size_t)b * KK * DD;

    float xr[8];
#pragma unroll
    for (int c = 0; c < 8; c++) xr[c] = x[lane + 32 * c];

    float pk[KK];
#pragma unroll
    for (int k = 0; k < KK; k++) {
        float p = 0.f;
#pragma unroll
        for (int c = 0; c < 8; c++) p = fmaf(xr[c], kb[k * DD + lane + 32 * c], p);
        pk[k] = p;
    }
#pragma unroll
    for (int o = 16; o; o >>= 1)
#pragma unroll
        for (int k = 0; k < KK; k++) pk[k] += __shfl_xor_sync(0xffffffffu, pk[k], o);

    if (lane < KK)
        g_xk[((size_t)b * SS + i) * KK + lane] = pk[lane];
}

// ================= kernel 2: HMMA recurrent kernel (fp16 hi/lo, 2-pass) =================
// C[e][k] = sum_d U[d][e]*h[k][d] ≈ (Uhi + Ulo) x Hhi  (drops Uhi x Hlo ~ 2^-11/step)
__global__ void __launch_bounds__(256, 2) __cluster_dims__(2, 1, 1)
rnn_mma_kernel(const float* __restrict__ X, const int* __restrict__ mask,
               const float* __restrict__ keys, const float* __restrict__ U,
               const float* __restrict__ V, float* __restrict__ out) {
    extern __shared__ __align__(16) unsigned char smraw[];
    MiscS* ms = (MiscS*)(smraw + OFF_MISC);
    float* kVs = (float*)(smraw + OFF_KV);

    const int tid = threadIdx.x;
    const int lane = tid & 31, w = tid >> 5;
    const int b = blockIdx.x >> 1;
    const uint32_t rank = cluster_rank();
    const uint32_t smbase = smem_u32(smraw);

    const int e0 = w * 16;
    const int gr = lane >> 2;
    const int gc = (lane & 3) * 2;
    const int el0 = e0 + gr;
    const int el1 = e0 + 8 + gr;
    const int eg0 = (int)rank * 128 + el0;
    const int eg1 = (int)rank * 128 + el1;

    // ---- load precomputed active list + init mbarriers ----
    const int n_act = g_nact[b];
    for (int idx = tid; idx < SS; idx += 256)
        ms->slist[idx] = g_slist[(size_t)b * SS + idx];
    if (tid == 0) {
        MBARRIER_INIT(smem_u32(&ms->mbar0), KK);    // 20 partial-arrivals per step
        MBARRIER_INIT(smem_u32(&ms->mbar1), 256);   // 256 h-arrivals per step
    }

    // ---- stage U^T HI (fp16), preload A frags, overwrite with LO ----
    for (int idx = tid; idx < 128 * DD; idx += 256) {
        const int el = idx & 127, d = idx >> 7;
        const float f = U[(size_t)d * DD + rank * 128 + el];
        *(unsigned short*)(smraw + OFF_ULO + el * PITCHB + d * 2) =
            __half_as_ushort(__float2half_rn(f));
    }
    __syncthreads();

    const uint32_t aoff = (uint32_t)(e0 + (lane & 7) + ((lane >> 3) & 1) * 8) * PITCHB
                        + (uint32_t)((lane >> 4) & 1) * 16;
    uint32_t uh[16][4];
#pragma unroll
    for (int kc = 0; kc < 16; kc++)
        LDSM4(uh[kc], smbase + OFF_ULO + aoff + (uint32_t)kc * 32);
    __syncthreads();

    for (int idx = tid; idx < 128 * DD; idx += 256) {
        const int el = idx & 127, d = idx >> 7;
        const float f = U[(size_t)d * DD + rank * 128 + el];
        const __half hi = __float2half_rn(f);
        *(unsigned short*)(smraw + OFF_ULO + el * PITCHB + d * 2) =
            __half_as_ushort(__float2half_rn(f - __half2float(hi)));
    }

    // zero h tile (rows 20..23 stay zero forever)
    {
        const uint4 z = make_uint4(0, 0, 0, 0);
        uint4* p = (uint4*)(smraw + OFF_HHI);
        for (int i = tid; i < (24 * PITCHB) / 16; i += 256) p[i] = z;
    }

    // kV table
    {
        const int kh = tid >> 7, el = tid & 127;
        float kvv[10];
#pragma unroll
        for (int j = 0; j < 10; j++) kvv[j] = 0.f;
        const float* kr = keys + (size_t)b * KK * DD + (size_t)kh * 10 * DD;
#pragma unroll 4
        for (int d = 0; d < DD; d++) {
            const float vv = V[(size_t)d * DD + rank * 128 + el];
#pragma unroll
            for (int j = 0; j < 10; j++) kvv[j] = fmaf(kr[j * DD + d], vv, kvv[j]);
        }
#pragma unroll
        for (int j = 0; j < 10; j++) kVs[(kh * 10 + j) * KVP + el] = kvv[j];
    }

    if (tid < KK && n_act > 0)
        ms->gbuf[tid] = 1.f / (1.f + __expf(-g_xk[((size_t)b * SS + 0) * KK + tid]));
    __syncthreads();
    CLUSTER_SYNC();   // mbarrier init + tiles visible cluster-wide before any remote traffic

    uint32_t peer_base;
    asm("mapa.shared::cluster.u32 %0, %1, %2;" : "=r"(peer_base) : "r"(smbase), "r"(rank ^ 1u));
    const uint32_t peer_rpart = peer_base + OFF_MISC + (uint32_t)offsetof(MiscS, rpart);
    const uint32_t peer_mbar0 = peer_base + OFF_MISC + (uint32_t)offsetof(MiscS, mbar0);
    const uint32_t peer_mbar1 = peer_base + OFF_MISC + (uint32_t)offsetof(MiscS, mbar1);
    const uint32_t loc_mbar0 = smem_u32(&ms->mbar0);
    const uint32_t loc_mbar1 = smem_u32(&ms->mbar1);

    const uint32_t bOff4 = (uint32_t)(8 * ((lane >> 4) & 1) + (lane & 7)) * PITCHB
                         + (uint32_t)((lane >> 3) & 1) * 16;
    const uint32_t bOff2 = (uint32_t)(16 + (lane & 7)) * PITCHB
                         + (uint32_t)((lane >> 3) & 1) * 16;
    const uint32_t hhi = smbase + OFF_HHI;
    const uint32_t ulo = smbase + OFF_ULO;

    // h state lives in registers, mirrored (fp16 hi) in the smem tile for the MMA
    float hreg[3][4];
#pragma unroll
    for (int nt = 0; nt < 3; nt++)
#pragma unroll
        for (int q = 0; q < 4; q++) hreg[nt][q] = 0.f;

    int ph = 0;
    for (int i = 0; i < n_act; i++) {
        const bool hasn = (i + 1 < n_act);
        const int sn = hasn ? (int)ms->slist[i + 1] : 0;
        const float xw0 = g_xw[((size_t)b * SS + i) * DD + eg0];
        const float xw1 = g_xw[((size_t)b * SS + i) * DD + eg1];
        float xn0 = 0.f, xn1 = 0.f;
        if (hasn) {
            xn0 = X[((size_t)b * SS + sn) * DD + eg0];
            xn1 = X[((size_t)b * SS + sn) * DD + eg1];
        }

        float c[3][4];
#pragma unroll
        for (int nt = 0; nt < 3; nt++)
#pragma unroll
            for (int q = 0; q < 4; q++) c[nt][q] = 0.f;

        // ---- 2-pass MMA: (Uhi + Ulo) x Hhi ----
#pragma unroll
        for (int kc = 0; kc < 16; kc++) {
            const uint32_t dofs = (uint32_t)kc * 32;
            uint32_t bh[4], b2[2], al[4];
            LDSM4(bh, hhi + bOff4 + dofs);
            LDSM2(b2, hhi + bOff2 + dofs);
            LDSM4(al, ulo + aoff + dofs);
            MMA16816(c[0], uh[kc], bh[0], bh[1]);
            MMA16816(c[1], uh[kc], bh[2], bh[3]);
            MMA16816(c[2], uh[kc], b2[0], b2[1]);
            MMA16816(c[0], al, bh[0], bh[1]);
            MMA16816(c[1], al, bh[2], bh[3]);
            MMA16816(c[2], al, b2[0], b2[1]);
        }

        float sq6[6], du6[6];
#pragma unroll
        for (int nt = 0; nt < 3; nt++) {
#pragma unroll
            for (int j = 0; j < 2; j++) {
                const int k = 8 * nt + gc + j;
                const bool val = (k < KK);
                const int kk = val ? k : 0;
                const float gv = val ? ms->gbuf[kk] : 0.f;
                const float kv0 = kVs[kk * KVP + el0];
                const float kv1 = kVs[kk * KVP + el1];
                float u0 = 0.f, u1 = 0.f;
                if (val) {
                    u0 = hreg[nt][j] + gv * fmaxf(c[nt][j] + kv0 + xw0, 0.f);
                    u1 = hreg[nt][2 + j] + gv * fmaxf(c[nt][2 + j] + kv1 + xw1, 0.f);
                }
                c[nt][j] = u0;
                c[nt][2 + j] = u1;
                sq6[2 * nt + j] = u0 * u0 + u1 * u1;
                du6[2 * nt + j] = xn0 * u0 + xn1 * u1;
            }
        }
#pragma unroll
        for (int o = 4; o <= 16; o <<= 1)
#pragma unroll
            for (int q = 0; q < 6; q++) {
                sq6[q] += __shfl_xor_sync(0xffffffffu, sq6[q], o);
                du6[q] += __shfl_xor_sync(0xffffffffu, du6[q], o);
            }
        if (lane < 4) {
#pragma unroll
            for (int q = 0; q < 6; q++) {
                const int k = 8 * (q >> 1) + gc + (q & 1);
                if (k < KK) {
                    ms->red[w][k] = sq6[q];
                    ms->red[w][KK + k] = du6[q];
                }
            }
        }
        __syncthreads();
        if (tid < KK) {
            float sq = 0.f, du = 0.f;
#pragma unroll
            for (int ww = 0; ww < 8; ww++) {
                sq += ms->red[ww][tid];
                du += ms->red[ww][KK + tid];
            }
            ms->tot[tid] = sq;
            ms->tot[KK + tid] = du;
            asm volatile("st.shared::cluster.f32 [%0], %1;" :: "r"(peer_rpart + tid * 4), "f"(sq) : "memory");
            asm volatile("st.shared::cluster.f32 [%0], %1;" :: "r"(peer_rpart + (KK + tid) * 4), "f"(du) : "memory");
            MBAR_ARRIVE_REMOTE(peer_mbar0);   // release: covers this thread's two stores
        }
        if (tid < KK) {
            MBAR_WAIT_CL(loc_mbar0, ph);      // peer's 20 partial pairs have landed
            const float sq = ms->tot[tid] + ms->rpart[tid];
            const float du = ms->tot[KK + tid] + ms->rpart[KK + tid];
            const float rinv = rsqrtf(fmaxf(sq, 1e-12f));
            ms->rbuf[tid] = rinv;
            if (hasn)
                ms->gbuf[tid] = 1.f / (1.f + __expf(-(rinv * du + g_xk[((size_t)b * SS + i + 1) * KK + tid])));
        }
        __syncthreads();

        // ---- normalize in regs + write fp16 h-hi to local + peer tiles ----
#pragma unroll
        for (int nt = 0; nt < 3; nt++) {
#pragma unroll
            for (int j = 0; j < 2; j++) {
                const int k = 8 * nt + gc + j;
                if (k < KK) {
                    const float rv = ms->rbuf[k];
                    const uint32_t roff = (uint32_t)k * PITCHB;
#pragma unroll
                    for (int rr = 0; rr < 2; rr++) {
                        const float hn = c[nt][2 * rr + j] * rv;
                        hreg[nt][2 * rr + j] = hn;
                        const unsigned short hb = __half_as_ushort(__float2half_rn(hn));
                        const uint32_t off = roff + (uint32_t)(rr ? eg1 : eg0) * 2;
                        asm volatile("st.shared.u16 [%0], %1;" :: "r"(smbase + OFF_HHI + off), "h"(hb) : "memory");
                        asm volatile("st.shared::cluster.u16 [%0], %1;" :: "r"(peer_base + OFF_HHI + off), "h"(hb) : "memory");
                    }
                }
            }
        }
        MBAR_ARRIVE_REMOTE(peer_mbar1);       // release: covers this thread's peer-tile stores
        __syncthreads();                      // local tile stores visible CTA-wide
        MBAR_WAIT_CL(loc_mbar1, ph);          // peer's half of our tile has landed
        ph ^= 1;
    }

    // ---- emit straight from registers ----
#pragma unroll
    for (int nt = 0; nt < 3; nt++) {
#pragma unroll
        for (int j = 0; j < 2; j++) {
            const int k = 8 * nt + gc + j;
            if (k < KK) {
                out[((size_t)b * KK + k) * DD + eg0] = hreg[nt][j];
                out[((size_t)b * KK + k) * DD + eg1] = hreg[nt][2 + j];
            }
        }
    }
    CLUSTER_SYNC();   // no CTA exits while peer DSMEM traffic may be in flight
}

extern "C" void kernel_launch(void* const* d_in, const int* in_sizes, int n_in,
                              void* d_out, int out_size) {
    const float* X = (const float*)d_in[0];
    const int* mask = (const int*)d_in[1];
    const float* keys = (const float*)d_in[2];
    const float* U = (const float*)d_in[3];
    const float* V = (const float*)d_in[4];
    const float* W = (const float*)d_in[5];
    float* out = (float*)d_out;

    cudaFuncSetAttribute(rnn_mma_kernel, cudaFuncAttributeMaxDynamicSharedMemorySize, SMEM_TOT);

    mask_kernel<<<BB, 256>>>(mask);
    xw_kernel<<<BB * (SS / 32), 256>>>(X, W);
    xk_kernel<<<BB * (SS / 8), 256>>>(X, keys);
    rnn_mma_kernel<<<2 * BB, 256, SMEM_TOT>>>(X, mask, keys, U, V, out);
}

// round 14
// speedup vs baseline: 1.6052x; 1.1202x over previous
#include <cuda_runtime.h>
#include <cuda_bf16.h>
#include <cuda_fp16.h>
#include <math.h>
#include <stdint.h>

// Problem constants
#define BB 256
#define SS 512
#define KK 20
#define DD 256
#define PITCHB 528   // bytes per fp16 row (264 elems): odd 16B count -> ldmatrix conflict-free
#define KVP 260      // kV table pitch (f32), full 256 e + stagger

// Precomputed scratch (static device globals: allocation-free)
__device__ float g_xw[(size_t)BB * SS * DD];            // xW[b][i][e]   (compact index i)
__device__ float g_xk[(size_t)BB * SS * KK];            // x.keys[b][i][k] (compact index i)
__device__ unsigned short g_slist[(size_t)BB * SS];     // active step indices per batch
__device__ int g_nact[BB];                              // active count per batch

// ================= packed f32x2 helpers (xw kernel) =================
__device__ __forceinline__ unsigned long long f2fma(unsigned long long a,
                                                    unsigned long long b,
                                                    unsigned long long c) {
    unsigned long long d;
    asm("fma.rn.f32x2 %0, %1, %2, %3;" : "=l"(d) : "l"(a), "l"(b), "l"(c));
    return d;
}
__device__ __forceinline__ unsigned long long pk2(float a) {
    unsigned int ai = __float_as_uint(a);
    return (((unsigned long long)ai) << 32) | (unsigned long long)ai;
}
__device__ __forceinline__ void upk2(unsigned long long p, float& lo, float& hi) {
    lo = __uint_as_float((unsigned int)(p & 0xffffffffull));
    hi = __uint_as_float((unsigned int)(p >> 32));
}

// ================= PTX helpers =================
__device__ __forceinline__ uint32_t smem_u32(const void* p) {
    uint32_t a;
    asm("{ .reg .u64 t; cvta.to.shared.u64 t, %1; cvt.u32.u64 %0, t; }" : "=r"(a) : "l"(p));
    return a;
}

#define LDSM4(r, addr) \
    asm volatile("ldmatrix.sync.aligned.m8n8.x4.shared.b16 {%0,%1,%2,%3}, [%4];" \
        : "=r"((r)[0]), "=r"((r)[1]), "=r"((r)[2]), "=r"((r)[3]) : "r"(addr))
#define LDSM2(r, addr) \
    asm volatile("ldmatrix.sync.aligned.m8n8.x2.shared.b16 {%0,%1}, [%2];" \
        : "=r"((r)[0]), "=r"((r)[1]) : "r"(addr))

// fp16 MMA: m16n8k16, f32 accumulate
#define MMA16816(c, a, b0, b1) \
    asm volatile("mma.sync.aligned.m16n8k16.row.col.f32.f16.f16.f32 " \
        "{%0,%1,%2,%3}, {%4,%5,%6,%7}, {%8,%9}, {%0,%1,%2,%3};" \
        : "+f"((c)[0]), "+f"((c)[1]), "+f"((c)[2]), "+f"((c)[3]) \
        : "r"((a)[0]), "r"((a)[1]), "r"((a)[2]), "r"((a)[3]), "r"(b0), "r"(b1))

// ================= shared memory layout (rnn kernel) =================
struct MiscS {
    float red[16][2 * KK];     // per-warp partials (sq | du)
    float gbuf[KK];
    float rbuf[KK];
    unsigned short slist[SS];
};
#define OFF_ULO 0                                 // U^T lo fp16 [256 e][256 d] (staged hi first)
#define OFF_HHI (256 * PITCHB)                    // h hi tile fp16 [24 k][256 d]
#define OFF_KV  (OFF_HHI + 24 * PITCHB)           // kV [20][KVP] f32
#define OFF_MISC (OFF_KV + KK * KVP * 4)
#define SMEM_TOT ((int)(OFF_MISC + sizeof(MiscS)))

// ================= kernel 0: mask compaction to global =================
__global__ void __launch_bounds__(256) mask_kernel(const int* __restrict__ mask) {
    __shared__ int wcnt[8];
    const int b = blockIdx.x;
    const int tid = threadIdx.x;
    const int lane = tid & 31, w = tid >> 5;

    int total = 0;
    for (int r = 0; r < 2; r++) {
        const int idx = r * 256 + tid;
        const int m = (mask[b * SS + idx] != 0);
        const unsigned bal = __ballot_sync(0xffffffffu, m);
        const int pre = __popc(bal & ((1u << lane) - 1));
        if (lane == 0) wcnt[w] = __popc(bal);
        __syncthreads();
        int woff = 0;
        for (int ww = 0; ww < w; ww++) woff += wcnt[ww];
        if (m) g_slist[(size_t)b * SS + total + woff + pre] = (unsigned short)idx;
        int rt = 0;
#pragma unroll
        for (int ww = 0; ww < 8; ww++) rt += wcnt[ww];
        total += rt;
        __syncthreads();
    }
    if (tid == 0) g_nact[b] = total;
}

// ================= kernel 1: xW for ACTIVE steps only (f32x2, proven) =================
__global__ void __launch_bounds__(256) xw_kernel(const float* __restrict__ X,
                                                 const float* __restrict__ W) {
    __shared__ float xt[DD][34];
    __shared__ unsigned short sl[32];
    const int cta = blockIdx.x;
    const int b = cta >> 4;
    const int s0 = (cta & 15) * 32;     // compact row base
    const int tid = threadIdx.x;

    const int n_act = g_nact[b];
    if (s0 >= n_act) return;

    if (tid < 32)
        sl[tid] = (s0 + tid < n_act) ? g_slist[(size_t)b * SS + s0 + tid] : (unsigned short)0;
    __syncthreads();

    for (int idx = tid; idx < 32 * DD; idx += 256) {
        const int ss = idx >> 8, d = idx & 255;
        xt[d][ss] = X[((size_t)b * SS + sl[ss]) * DD + d];
    }
    __syncthreads();

    unsigned long long acc[16];
#pragma unroll
    for (int i = 0; i < 16; i++) acc[i] = 0ull;

    float ua[4], ub[4], un[4];
#pragma unroll
    for (int j = 0; j < 4; j++) ua[j] = W[j * DD + tid];
#pragma unroll
    for (int j = 0; j < 4; j++) ub[j] = W[(4 + j) * DD + tid];
    for (int db = 0; db < 64; db++) {
        const int dn = db * 4 + 8;
        if (dn < DD) {
#pragma unroll
            for (int j = 0; j < 4; j++) un[j] = W[(dn + j) * DD + tid];
        } else {
#pragma unroll
            for (int j = 0; j < 4; j++) un[j] = 0.f;
        }
#pragma unroll
        for (int dd = 0; dd < 4; dd++) {
            const int d = db * 4 + dd;
            const unsigned long long* xr = (const unsigned long long*)xt[d];
            unsigned long long ww = pk2(ua[dd]);
#pragma unroll
            for (int j = 0; j < 16; j++) acc[j] = f2fma(xr[j], ww, acc[j]);
        }
#pragma unroll
        for (int j = 0; j < 4; j++) { ua[j] = ub[j]; ub[j] = un[j]; }
    }
#pragma unroll
    for (int j = 0; j < 16; j++) {
        float lo, hi;
        upk2(acc[j], lo, hi);
        const int r0 = s0 + 2 * j, r1 = s0 + 2 * j + 1;
        if (r0 < n_act) g_xw[((size_t)b * SS + r0) * DD + tid] = lo;
        if (r1 < n_act) g_xw[((size_t)b * SS + r1) * DD + tid] = hi;
    }
}

// ================= kernel 1b: xk for ACTIVE steps only =================
__global__ void __launch_bounds__(256) xk_kernel(const float* __restrict__ X,
                                                 const float* __restrict__ keys) {
    const int b = blockIdx.x >> 6;
    const int i = ((blockIdx.x & 63) << 3) + (threadIdx.x >> 5);
    const int lane = threadIdx.x & 31;
    if (i >= g_nact[b]) return;    // whole warp shares i
    const int s = g_slist[(size_t)b * SS + i];
    const float* x = X + ((size_t)b * SS + s) * DD;
    const float* kb = keys + (size_t)b * KK * DD;

    float xr[8];
#pragma unroll
    for (int c = 0; c < 8; c++) xr[c] = x[lane + 32 * c];

    float pk[KK];
#pragma unroll
    for (int k = 0; k < KK; k++) {
        float p = 0.f;
#pragma unroll
        for (int c = 0; c < 8; c++) p = fmaf(xr[c], kb[k * DD + lane + 32 * c], p);
        pk[k] = p;
    }
#pragma unroll
    for (int o = 16; o; o >>= 1)
#pragma unroll
        for (int k = 0; k < KK; k++) pk[k] += __shfl_xor_sync(0xffffffffu, pk[k], o);

    if (lane < KK)
        g_xk[((size_t)b * SS + i) * KK + lane] = pk[lane];
}

// ================= kernel 2: single-CTA HMMA recurrent kernel (512 threads) =================
// One CTA per batch; 16 warps x 16 e-columns cover the full D=256. No cluster, no DSMEM.
// C[e][k] = sum_d U[d][e]*h[k][d] ≈ (Uhi + Ulo) x Hhi  (fp16 hi/lo, 2-pass)
__global__ void __launch_bounds__(512, 1)
rnn_mma_kernel(const float* __restrict__ X, const int* __restrict__ mask,
               const float* __restrict__ keys, const float* __restrict__ U,
               const float* __restrict__ V, float* __restrict__ out) {
    extern __shared__ __align__(16) unsigned char smraw[];
    MiscS* ms = (MiscS*)(smraw + OFF_MISC);
    float* kVs = (float*)(smraw + OFF_KV);

    const int tid = threadIdx.x;
    const int lane = tid & 31, w = tid >> 5;   // 16 warps
    const int b = blockIdx.x;
    const uint32_t smbase = smem_u32(smraw);

    const int e0 = w * 16;                      // warp's 16 e-columns
    const int gr = lane >> 2;
    const int gc = (lane & 3) * 2;
    const int eg0 = e0 + gr;
    const int eg1 = e0 + 8 + gr;

    // ---- load precomputed active list ----
    const int n_act = g_nact[b];
    for (int idx = tid; idx < SS; idx += 512)
        ms->slist[idx] = g_slist[(size_t)b * SS + idx];

    // ---- stage U^T HI (fp16, full 256 e), preload A frags, overwrite with LO ----
    for (int idx = tid; idx < 256 * DD; idx += 512) {
        const int el = idx & 255, d = idx >> 8;
        const float f = U[(size_t)d * DD + el];
        *(unsigned short*)(smraw + OFF_ULO + el * PITCHB + d * 2) =
            __half_as_ushort(__float2half_rn(f));
    }
    __syncthreads();

    const uint32_t aoff = (uint32_t)(e0 + (lane & 7) + ((lane >> 3) & 1) * 8) * PITCHB
                        + (uint32_t)((lane >> 4) & 1) * 16;
    uint32_t uh[16][4];
#pragma unroll
    for (int kc = 0; kc < 16; kc++)
        LDSM4(uh[kc], smbase + OFF_ULO + aoff + (uint32_t)kc * 32);
    __syncthreads();

    for (int idx = tid; idx < 256 * DD; idx += 512) {
        const int el = idx & 255, d = idx >> 8;
        const float f = U[(size_t)d * DD + el];
        const __half hi = __float2half_rn(f);
        *(unsigned short*)(smraw + OFF_ULO + el * PITCHB + d * 2) =
            __half_as_ushort(__float2half_rn(f - __half2float(hi)));
    }

    // zero h tile (rows 20..23 stay zero forever)
    {
        const uint4 z = make_uint4(0, 0, 0, 0);
        uint4* p = (uint4*)(smraw + OFF_HHI);
        for (int i = tid; i < (24 * PITCHB) / 16; i += 512) p[i] = z;
    }

    // kV table [20][KVP] for full e range; thread (kh, el): 10 k values
    {
        const int kh = tid >> 8, el = tid & 255;
        float kvv[10];
#pragma unroll
        for (int j = 0; j < 10; j++) kvv[j] = 0.f;
        const float* kr = keys + (size_t)b * KK * DD + (size_t)kh * 10 * DD;
#pragma unroll 4
        for (int d = 0; d < DD; d++) {
            const float vv = V[(size_t)d * DD + el];
#pragma unroll
            for (int j = 0; j < 10; j++) kvv[j] = fmaf(kr[j * DD + d], vv, kvv[j]);
        }
#pragma unroll
        for (int j = 0; j < 10; j++) kVs[(kh * 10 + j) * KVP + el] = kvv[j];
    }

    if (tid < KK && n_act > 0)
        ms->gbuf[tid] = 1.f / (1.f + __expf(-g_xk[((size_t)b * SS + 0) * KK + tid]));
    __syncthreads();

    const uint32_t bOff4 = (uint32_t)(8 * ((lane >> 4) & 1) + (lane & 7)) * PITCHB
                         + (uint32_t)((lane >> 3) & 1) * 16;
    const uint32_t bOff2 = (uint32_t)(16 + (lane & 7)) * PITCHB
                         + (uint32_t)((lane >> 3) & 1) * 16;
    const uint32_t hhi = smbase + OFF_HHI;
    const uint32_t ulo = smbase + OFF_ULO;

    // h state lives in registers, mirrored (fp16 hi) in the smem tile for the MMA
    float hreg[3][4];
#pragma unroll
    for (int nt = 0; nt < 3; nt++)
#pragma unroll
        for (int q = 0; q < 4; q++) hreg[nt][q] = 0.f;

    for (int i = 0; i < n_act; i++) {
        const bool hasn = (i + 1 < n_act);
        const int sn = hasn ? (int)ms->slist[i + 1] : 0;
        const float xw0 = g_xw[((size_t)b * SS + i) * DD + eg0];
        const float xw1 = g_xw[((size_t)b * SS + i) * DD + eg1];
        float xn0 = 0.f, xn1 = 0.f;
        if (hasn) {
            xn0 = X[((size_t)b * SS + sn) * DD + eg0];
            xn1 = X[((size_t)b * SS + sn) * DD + eg1];
        }

        float c[3][4];
#pragma unroll
        for (int nt = 0; nt < 3; nt++)
#pragma unroll
            for (int q = 0; q < 4; q++) c[nt][q] = 0.f;

        // ---- 2-pass MMA: (Uhi + Ulo) x Hhi ----
#pragma unroll
        for (int kc = 0; kc < 16; kc++) {
            const uint32_t dofs = (uint32_t)kc * 32;
            uint32_t bh[4], b2[2], al[4];
            LDSM4(bh, hhi + bOff4 + dofs);
            LDSM2(b2, hhi + bOff2 + dofs);
            LDSM4(al, ulo + aoff + dofs);
            MMA16816(c[0], uh[kc], bh[0], bh[1]);
            MMA16816(c[1], uh[kc], bh[2], bh[3]);
            MMA16816(c[2], uh[kc], b2[0], b2[1]);
            MMA16816(c[0], al, bh[0], bh[1]);
            MMA16816(c[1], al, bh[2], bh[3]);
            MMA16816(c[2], al, b2[0], b2[1]);
        }

        float sq6[6], du6[6];
#pragma unroll
        for (int nt = 0; nt < 3; nt++) {
#pragma unroll
            for (int j = 0; j < 2; j++) {
                const int k = 8 * nt + gc + j;
                const bool val = (k < KK);
                const int kk = val ? k : 0;
                const float gv = val ? ms->gbuf[kk] : 0.f;
                const float kv0 = kVs[kk * KVP + eg0];
                const float kv1 = kVs[kk * KVP + eg1];
                float u0 = 0.f, u1 = 0.f;
                if (val) {
                    u0 = hreg[nt][j] + gv * fmaxf(c[nt][j] + kv0 + xw0, 0.f);
                    u1 = hreg[nt][2 + j] + gv * fmaxf(c[nt][2 + j] + kv1 + xw1, 0.f);
                }
                c[nt][j] = u0;
                c[nt][2 + j] = u1;
                sq6[2 * nt + j] = u0 * u0 + u1 * u1;
                du6[2 * nt + j] = xn0 * u0 + xn1 * u1;
            }
        }
#pragma unroll
        for (int o = 4; o <= 16; o <<= 1)
#pragma unroll
            for (int q = 0; q < 6; q++) {
                sq6[q] += __shfl_xor_sync(0xffffffffu, sq6[q], o);
                du6[q] += __shfl_xor_sync(0xffffffffu, du6[q], o);
            }
        if (lane < 4) {
#pragma unroll
            for (int q = 0; q < 6; q++) {
                const int k = 8 * (q >> 1) + gc + (q & 1);
                if (k < KK) {
                    ms->red[w][k] = sq6[q];
                    ms->red[w][KK + k] = du6[q];
                }
            }
        }
        __syncthreads();
        if (tid < KK) {
            float sq = 0.f, du = 0.f;
#pragma unroll
            for (int ww = 0; ww < 16; ww++) {
                sq += ms->red[ww][tid];
                du += ms->red[ww][KK + tid];
            }
            const float rinv = rsqrtf(fmaxf(sq, 1e-12f));
            ms->rbuf[tid] = rinv;
            if (hasn)
                ms->gbuf[tid] = 1.f / (1.f + __expf(-(rinv * du + g_xk[((size_t)b * SS + i + 1) * KK + tid])));
        }
        __syncthreads();

        // ---- normalize in regs + write fp16 h-hi to the local tile ----
#pragma unroll
        for (int nt = 0; nt < 3; nt++) {
#pragma unroll
            for (int j = 0; j < 2; j++) {
                const int k = 8 * nt + gc + j;
                if (k < KK) {
                    const float rv = ms->rbuf[k];
                    const uint32_t roff = (uint32_t)k * PITCHB;
#pragma unroll
                    for (int rr = 0; rr < 2; rr++) {
                        const float hn = c[nt][2 * rr + j] * rv;
                        hreg[nt][2 * rr + j] = hn;
                        const unsigned short hb = __half_as_ushort(__float2half_rn(hn));
                        const uint32_t off = roff + (uint32_t)(rr ? eg1 : eg0) * 2;
                        asm volatile("st.shared.u16 [%0], %1;" :: "r"(smbase + OFF_HHI + off), "h"(hb) : "memory");
                    }
                }
            }
        }
        __syncthreads();   // h tile stable for next step's LDSM
    }

    // ---- emit straight from registers ----
#pragma unroll
    for (int nt = 0; nt < 3; nt++) {
#pragma unroll
        for (int j = 0; j < 2; j++) {
            const int k = 8 * nt + gc + j;
            if (k < KK) {
                out[((size_t)b * KK + k) * DD + eg0] = hreg[nt][j];
                out[((size_t)b * KK + k) * DD + eg1] = hreg[nt][2 + j];
            }
        }
    }
}

extern "C" void kernel_launch(void* const* d_in, const int* in_sizes, int n_in,
                              void* d_out, int out_size) {
    const float* X = (const float*)d_in[0];
    const int* mask = (const int*)d_in[1];
    const float* keys = (const float*)d_in[2];
    const float* U = (const float*)d_in[3];
    const float* V = (const float*)d_in[4];
    const float* W = (const float*)d_in[5];
    float* out = (float*)d_out;

    cudaFuncSetAttribute(rnn_mma_kernel, cudaFuncAttributeMaxDynamicSharedMemorySize, SMEM_TOT);

    mask_kernel<<<BB, 256>>>(mask);
    xw_kernel<<<BB * (SS / 32), 256>>>(X, W);
    xk_kernel<<<BB * (SS / 8), 256>>>(X, keys);
    rnn_mma_kernel<<<BB, 512, SMEM_TOT>>>(X, mask, keys, U, V, out);
}

// round 15
// speedup vs baseline: 1.9516x; 1.2158x over previous
#include <cuda_runtime.h>
#include <cuda_bf16.h>
#include <cuda_fp16.h>
#include <math.h>
#include <stdint.h>

// Problem constants
#define BB 256
#define SS 512
#define KK 20
#define DD 256
#define PITCHB 528   // bytes per fp16 row (264 elems): odd 16B count -> ldmatrix conflict-free
#define KVP 260      // kV table pitch (f32)

// Precomputed scratch (static device globals: allocation-free)
__device__ float g_xw[(size_t)BB * SS * DD];            // xW[b][i][e]   (compact index i)
__device__ float g_xk[(size_t)BB * SS * KK];            // x.keys[b][i][k] (compact index i)
__device__ unsigned short g_slist[(size_t)BB * SS];     // active step indices per batch
__device__ int g_nact[BB];                              // active count per batch

// ================= packed f32x2 helpers (xw kernel) =================
__device__ __forceinline__ unsigned long long f2fma(unsigned long long a,
                                                    unsigned long long b,
                                                    unsigned long long c) {
    unsigned long long d;
    asm("fma.rn.f32x2 %0, %1, %2, %3;" : "=l"(d) : "l"(a), "l"(b), "l"(c));
    return d;
}
__device__ __forceinline__ unsigned long long pk2(float a) {
    unsigned int ai = __float_as_uint(a);
    return (((unsigned long long)ai) << 32) | (unsigned long long)ai;
}
__device__ __forceinline__ void upk2(unsigned long long p, float& lo, float& hi) {
    lo = __uint_as_float((unsigned int)(p & 0xffffffffull));
    hi = __uint_as_float((unsigned int)(p >> 32));
}

// ================= PTX helpers =================
__device__ __forceinline__ uint32_t smem_u32(const void* p) {
    uint32_t a;
    asm("{ .reg .u64 t; cvta.to.shared.u64 t, %1; cvt.u32.u64 %0, t; }" : "=r"(a) : "l"(p));
    return a;
}

#define LDSM4(r, addr) \
    asm volatile("ldmatrix.sync.aligned.m8n8.x4.shared.b16 {%0,%1,%2,%3}, [%4];" \
        : "=r"((r)[0]), "=r"((r)[1]), "=r"((r)[2]), "=r"((r)[3]) : "r"(addr))
#define LDSM2(r, addr) \
    asm volatile("ldmatrix.sync.aligned.m8n8.x2.shared.b16 {%0,%1}, [%2];" \
        : "=r"((r)[0]), "=r"((r)[1]) : "r"(addr))

// fp16 MMA: m16n8k16, f32 accumulate
#define MMA16816(c, a, b0, b1) \
    asm volatile("mma.sync.aligned.m16n8k16.row.col.f32.f16.f16.f32 " \
        "{%0,%1,%2,%3}, {%4,%5,%6,%7}, {%8,%9}, {%0,%1,%2,%3};" \
        : "+f"((c)[0]), "+f"((c)[1]), "+f"((c)[2]), "+f"((c)[3]) \
        : "r"((a)[0]), "r"((a)[1]), "r"((a)[2]), "r"((a)[3]), "r"(b0), "r"(b1))

// ================= shared memory layout (rnn kernel) =================
struct MiscS {
    float red[16][2 * KK];     // per-warp partials (sq | du)
    float gbuf[KK];
    float rbuf[KK];
    unsigned short slist[SS];
};
#define TILEB (24 * PITCHB)
#define OFF_USTAGE 0                              // U^T hi fp16 [256 e][256 d], one-time staging
#define OFF_HA0 0                                 // h tile A (overlaps USTAGE after frag preload? NO -> placed after)
// Layout: staging region reused is risky; keep disjoint simple layout:
//   [0, 256*PITCHB)            : U staging (used once at init)
//   [256*PITCHB, +TILEB)       : h tile 0
//   [.., +TILEB)               : h tile 1
//   [.., +KV)                  : kV
#define OFF_HT0 (256 * PITCHB)
#define OFF_HT1 (OFF_HT0 + TILEB)
#define OFF_KV  (OFF_HT1 + TILEB)
#define OFF_MISC (OFF_KV + KK * KVP * 4)
#define SMEM_TOT ((int)(OFF_MISC + sizeof(MiscS)))

// ================= kernel 0: mask compaction to global =================
__global__ void __launch_bounds__(256) mask_kernel(const int* __restrict__ mask) {
    __shared__ int wcnt[8];
    const int b = blockIdx.x;
    const int tid = threadIdx.x;
    const int lane = tid & 31, w = tid >> 5;

    int total = 0;
    for (int r = 0; r < 2; r++) {
        const int idx = r * 256 + tid;
        const int m = (mask[b * SS + idx] != 0);
        const unsigned bal = __ballot_sync(0xffffffffu, m);
        const int pre = __popc(bal & ((1u << lane) - 1));
        if (lane == 0) wcnt[w] = __popc(bal);
        __syncthreads();
        int woff = 0;
        for (int ww = 0; ww < w; ww++) woff += wcnt[ww];
        if (m) g_slist[(size_t)b * SS + total + woff + pre] = (unsigned short)idx;
        int rt = 0;
#pragma unroll
        for (int ww = 0; ww < 8; ww++) rt += wcnt[ww];
        total += rt;
        __syncthreads();
    }
    if (tid == 0) g_nact[b] = total;
}

// ================= kernel 1: xW for ACTIVE steps only (f32x2, proven) =================
__global__ void __launch_bounds__(256) xw_kernel(const float* __restrict__ X,
                                                 const float* __restrict__ W) {
    __shared__ float xt[DD][34];
    __shared__ unsigned short sl[32];
    const int cta = blockIdx.x;
    const int b = cta >> 4;
    const int s0 = (cta & 15) * 32;     // compact row base
    const int tid = threadIdx.x;

    const int n_act = g_nact[b];
    if (s0 >= n_act) return;

    if (tid < 32)
        sl[tid] = (s0 + tid < n_act) ? g_slist[(size_t)b * SS + s0 + tid] : (unsigned short)0;
    __syncthreads();

    for (int idx = tid; idx < 32 * DD; idx += 256) {
        const int ss = idx >> 8, d = idx & 255;
        xt[d][ss] = X[((size_t)b * SS + sl[ss]) * DD + d];
    }
    __syncthreads();

    unsigned long long acc[16];
#pragma unroll
    for (int i = 0; i < 16; i++) acc[i] = 0ull;

    float ua[4], ub[4], un[4];
#pragma unroll
    for (int j = 0; j < 4; j++) ua[j] = W[j * DD + tid];
#pragma unroll
    for (int j = 0; j < 4; j++) ub[j] = W[(4 + j) * DD + tid];
    for (int db = 0; db < 64; db++) {
        const int dn = db * 4 + 8;
        if (dn < DD) {
#pragma unroll
            for (int j = 0; j < 4; j++) un[j] = W[(dn + j) * DD + tid];
        } else {
#pragma unroll
            for (int j = 0; j < 4; j++) un[j] = 0.f;
        }
#pragma unroll
        for (int dd = 0; dd < 4; dd++) {
            const int d = db * 4 + dd;
            const unsigned long long* xr = (const unsigned long long*)xt[d];
            unsigned long long ww = pk2(ua[dd]);
#pragma unroll
            for (int j = 0; j < 16; j++) acc[j] = f2fma(xr[j], ww, acc[j]);
        }
#pragma unroll
        for (int j = 0; j < 4; j++) { ua[j] = ub[j]; ub[j] = un[j]; }
    }
#pragma unroll
    for (int j = 0; j < 16; j++) {
        float lo, hi;
        upk2(acc[j], lo, hi);
        const int r0 = s0 + 2 * j, r1 = s0 + 2 * j + 1;
        if (r0 < n_act) g_xw[((size_t)b * SS + r0) * DD + tid] = lo;
        if (r1 < n_act) g_xw[((size_t)b * SS + r1) * DD + tid] = hi;
    }
}

// ================= kernel 1b: xk for ACTIVE steps only =================
__global__ void __launch_bounds__(256) xk_kernel(const float* __restrict__ X,
                                                 const float* __restrict__ keys) {
    const int b = blockIdx.x >> 6;
    const int i = ((blockIdx.x & 63) << 3) + (threadIdx.x >> 5);
    const int lane = threadIdx.x & 31;
    if (i >= g_nact[b]) return;    // whole warp shares i
    const int s = g_slist[(size_t)b * SS + i];
    const float* x = X + ((size_t)b * SS + s) * DD;
    const float* kb = keys + (size_t)b * KK * DD;

    float xr[8];
#pragma unroll
    for (int c = 0; c < 8; c++) xr[c] = x[lane + 32 * c];

    float pk[KK];
#pragma unroll
    for (int k = 0; k < KK; k++) {
        float p = 0.f;
#pragma unroll
        for (int c = 0; c < 8; c++) p = fmaf(xr[c], kb[k * DD + lane + 32 * c], p);
        pk[k] = p;
    }
#pragma unroll
    for (int o = 16; o; o >>= 1)
#pragma unroll
        for (int k = 0; k < KK; k++) pk[k] += __shfl_xor_sync(0xffffffffu, pk[k], o);

    if (lane < KK)
        g_xk[((size_t)b * SS + i) * KK + lane] = pk[lane];
}

// ================= kernel 2: single-CTA HMMA recurrent kernel =================
// 512 threads; 16 warps x 16 e-columns. Single-pass fp16 MMA (Uhi x UPDhi),
// DEFERRED normalization: h tile holds UNNORMALIZED upd; C_norm = rinv_prev * C_raw.
// Double-buffered h tile -> 2 __syncthreads per step.
__global__ void __launch_bounds__(512, 1)
rnn_mma_kernel(const float* __restrict__ X, const int* __restrict__ mask,
               const float* __restrict__ keys, const float* __restrict__ U,
               const float* __restrict__ V, float* __restrict__ out) {
    extern __shared__ __align__(16) unsigned char smraw[];
    MiscS* ms = (MiscS*)(smraw + OFF_MISC);
    float* kVs = (float*)(smraw + OFF_KV);

    const int tid = threadIdx.x;
    const int lane = tid & 31, w = tid >> 5;   // 16 warps
    const int b = blockIdx.x;
    const uint32_t smbase = smem_u32(smraw);

    const int e0 = w * 16;                      // warp's 16 e-columns
    const int gr = lane >> 2;
    const int gc = (lane & 3) * 2;
    const int eg0 = e0 + gr;
    const int eg1 = e0 + 8 + gr;

    // ---- load precomputed active list ----
    const int n_act = g_nact[b];
    for (int idx = tid; idx < SS; idx += 512)
        ms->slist[idx] = g_slist[(size_t)b * SS + idx];

    // ---- stage U^T HI (fp16, full 256 e), preload A frags (one-time) ----
    for (int idx = tid; idx < 256 * DD; idx += 512) {
        const int el = idx & 255, d = idx >> 8;
        const float f = U[(size_t)d * DD + el];
        *(unsigned short*)(smraw + OFF_USTAGE + el * PITCHB + d * 2) =
            __half_as_ushort(__float2half_rn(f));
    }
    __syncthreads();

    const uint32_t aoff = (uint32_t)(e0 + (lane & 7) + ((lane >> 3) & 1) * 8) * PITCHB
                        + (uint32_t)((lane >> 4) & 1) * 16;
    uint32_t uh[16][4];
#pragma unroll
    for (int kc = 0; kc < 16; kc++)
        LDSM4(uh[kc], smbase + OFF_USTAGE + aoff + (uint32_t)kc * 32);

    // zero both h tiles (rows 20..23 stay zero forever)
    {
        const uint4 z = make_uint4(0, 0, 0, 0);
        uint4* p = (uint4*)(smraw + OFF_HT0);
        for (int i = tid; i < (2 * TILEB) / 16; i += 512) p[i] = z;
    }

    // kV table [20][KVP] full e range; thread (kh, el): 10 k values
    {
        const int kh = tid >> 8, el = tid & 255;
        float kvv[10];
#pragma unroll
        for (int j = 0; j < 10; j++) kvv[j] = 0.f;
        const float* kr = keys + (size_t)b * KK * DD + (size_t)kh * 10 * DD;
#pragma unroll 4
        for (int d = 0; d < DD; d++) {
            const float vv = V[(size_t)d * DD + el];
#pragma unroll
            for (int j = 0; j < 10; j++) kvv[j] = fmaf(kr[j * DD + d], vv, kvv[j]);
        }
#pragma unroll
        for (int j = 0; j < 10; j++) kVs[(kh * 10 + j) * KVP + el] = kvv[j];
    }

    if (tid < KK && n_act > 0) {
        ms->gbuf[tid] = 1.f / (1.f + __expf(-g_xk[((size_t)b * SS + 0) * KK + tid]));
        ms->rbuf[tid] = 1.f;   // rinv_prev for step 0 (h=0, tile=0 -> exact)
    }
    __syncthreads();

    const uint32_t bOff4 = (uint32_t)(8 * ((lane >> 4) & 1) + (lane & 7)) * PITCHB
                         + (uint32_t)((lane >> 3) & 1) * 16;
    const uint32_t bOff2 = (uint32_t)(16 + (lane & 7)) * PITCHB
                         + (uint32_t)((lane >> 3) & 1) * 16;
    const uint32_t ht[2] = { smbase + OFF_HT0, smbase + OFF_HT1 };

    // hreg holds UNNORMALIZED upd from the previous step (0 initially)
    float hreg[3][4];
#pragma unroll
    for (int nt = 0; nt < 3; nt++)
#pragma unroll
        for (int q = 0; q < 4; q++) hreg[nt][q] = 0.f;

    for (int i = 0; i < n_act; i++) {
        const uint32_t rtile = ht[i & 1];          // holds upd_{i-1}
        const uint32_t wtile = ht[(i + 1) & 1];    // will hold upd_i
        const bool hasn = (i + 1 < n_act);
        const int sn = hasn ? (int)ms->slist[i + 1] : 0;
        const float xw0 = g_xw[((size_t)b * SS + i) * DD + eg0];
        const float xw1 = g_xw[((size_t)b * SS + i) * DD + eg1];
        float xn0 = 0.f, xn1 = 0.f;
        if (hasn) {
            xn0 = X[((size_t)b * SS + sn) * DD + eg0];
            xn1 = X[((size_t)b * SS + sn) * DD + eg1];
        }

        float c[3][4];
#pragma unroll
        for (int nt = 0; nt < 3; nt++)
#pragma unroll
            for (int q = 0; q < 4; q++) c[nt][q] = 0.f;

        // ---- single-pass MMA: Uhi x UPDhi (unnormalized) ----
#pragma unroll
        for (int kc = 0; kc < 16; kc++) {
            const uint32_t dofs = (uint32_t)kc * 32;
            uint32_t bh[4], b2[2];
            LDSM4(bh, rtile + bOff4 + dofs);
            LDSM2(b2, rtile + bOff2 + dofs);
            MMA16816(c[0], uh[kc], bh[0], bh[1]);
            MMA16816(c[1], uh[kc], bh[2], bh[3]);
            MMA16816(c[2], uh[kc], b2[0], b2[1]);
        }

        // ---- epilogue: deferred normalization + update + tile write + partials ----
        float sq6[6], du6[6];
#pragma unroll
        for (int nt = 0; nt < 3; nt++) {
#pragma unroll
            for (int j = 0; j < 2; j++) {
                const int k = 8 * nt + gc + j;
                const bool val = (k < KK);
                const int kk = val ? k : 0;
                const float gv = val ? ms->gbuf[kk] : 0.f;
                const float rv = ms->rbuf[kk];            // rinv_{i-1}
                const float kv0 = kVs[kk * KVP + eg0];
                const float kv1 = kVs[kk * KVP + eg1];
                float u0 = 0.f, u1 = 0.f;
                if (val) {
                    u0 = rv * hreg[nt][j] + gv * fmaxf(rv * c[nt][j] + kv0 + xw0, 0.f);
                    u1 = rv * hreg[nt][2 + j] + gv * fmaxf(rv * c[nt][2 + j] + kv1 + xw1, 0.f);
                    // write UNNORMALIZED upd to the write tile NOW (off the rinv path)
                    const uint32_t roff = (uint32_t)k * PITCHB;
                    const unsigned short b0 = __half_as_ushort(__float2half_rn(u0));
                    const unsigned short b1 = __half_as_ushort(__float2half_rn(u1));
                    asm volatile("st.shared.u16 [%0], %1;" :: "r"(wtile + roff + (uint32_t)eg0 * 2), "h"(b0) : "memory");
                    asm volatile("st.shared.u16 [%0], %1;" :: "r"(wtile + roff + (uint32_t)eg1 * 2), "h"(b1) : "memory");
                }
                hreg[nt][j] = u0;
                hreg[nt][2 + j] = u1;
                sq6[2 * nt + j] = u0 * u0 + u1 * u1;
                du6[2 * nt + j] = xn0 * u0 + xn1 * u1;
            }
        }
#pragma unroll
        for (int o = 4; o <= 16; o <<= 1)
#pragma unroll
            for (int q = 0; q < 6; q++) {
                sq6[q] += __shfl_xor_sync(0xffffffffu, sq6[q], o);
                du6[q] += __shfl_xor_sync(0xffffffffu, du6[q], o);
            }
        if (lane < 4) {
#pragma unroll
            for (int q = 0; q < 6; q++) {
                const int k = 8 * (q >> 1) + gc + (q & 1);
                if (k < KK) {
                    ms->red[w][k] = sq6[q];
                    ms->red[w][KK + k] = du6[q];
                }
            }
        }
        __syncthreads();   // bar1: tile writes + red visible
        if (tid < KK) {
            float sq = 0.f, du = 0.f;
#pragma unroll
            for (int ww = 0; ww < 16; ww++) {
                sq += ms->red[ww][tid];
                du += ms->red[ww][KK + tid];
            }
            const float rinv = rsqrtf(fmaxf(sq, 1e-12f));
            ms->rbuf[tid] = rinv;
            if (hasn)
                ms->gbuf[tid] = 1.f / (1.f + __expf(-(rinv * du + g_xk[((size_t)b * SS + i + 1) * KK + tid])));
        }
        __syncthreads();   // bar2: rbuf/gbuf ready
    }

    // ---- emit: apply final rinv to register state ----
#pragma unroll
    for (int nt = 0; nt < 3; nt++) {
#pragma unroll
        for (int j = 0; j < 2; j++) {
            const int k = 8 * nt + gc + j;
            if (k < KK) {
                const float rv = ms->rbuf[k];
                out[((size_t)b * KK + k) * DD + eg0] = hreg[nt][j] * rv;
                out[((size_t)b * KK + k) * DD + eg1] = hreg[nt][2 + j] * rv;
            }
        }
    }
}

extern "C" void kernel_launch(void* const* d_in, const int* in_sizes, int n_in,
                              void* d_out, int out_size) {
    const float* X = (const float*)d_in[0];
    const int* mask = (const int*)d_in[1];
    const float* keys = (const float*)d_in[2];
    const float* U = (const float*)d_in[3];
    const float* V = (const float*)d_in[4];
    const float* W = (const float*)d_in[5];
    float* out = (float*)d_out;

    cudaFuncSetAttribute(rnn_mma_kernel, cudaFuncAttributeMaxDynamicSharedMemorySize, SMEM_TOT);

    mask_kernel<<<BB, 256>>>(mask);
    xw_kernel<<<BB * (SS / 32), 256>>>(X, W);
    xk_kernel<<<BB * (SS / 8), 256>>>(X, keys);
    rnn_mma_kernel<<<BB, 512, SMEM_TOT>>>(X, mask, keys, U, V, out);
}

// round 16
// speedup vs baseline: 2.1056x; 1.0789x over previous
#include <cuda_runtime.h>
#include <cuda_bf16.h>
#include <cuda_fp16.h>
#include <math.h>
#include <stdint.h>

// Problem constants
#define BB 256
#define SS 512
#define KK 20
#define DD 256
#define PITCHB 528   // bytes per fp16 row (264 elems): odd 16B count -> ldmatrix conflict-free
#define KVP 260      // kV table pitch (f32)

// Precomputed scratch (static device globals: allocation-free)
__device__ float g_xw[(size_t)BB * SS * DD];            // xW[b][i][e]   (compact index i)
__device__ float g_xk[(size_t)BB * SS * KK];            // x.keys[b][i][k] (compact index i)
__device__ unsigned short g_slist[(size_t)BB * SS];     // active step indices per batch
__device__ int g_nact[BB];                              // active count per batch

// ================= packed f32x2 helpers (xw kernel) =================
__device__ __forceinline__ unsigned long long f2fma(unsigned long long a,
                                                    unsigned long long b,
                                                    unsigned long long c) {
    unsigned long long d;
    asm("fma.rn.f32x2 %0, %1, %2, %3;" : "=l"(d) : "l"(a), "l"(b), "l"(c));
    return d;
}
__device__ __forceinline__ unsigned long long pk2(float a) {
    unsigned int ai = __float_as_uint(a);
    return (((unsigned long long)ai) << 32) | (unsigned long long)ai;
}
__device__ __forceinline__ void upk2(unsigned long long p, float& lo, float& hi) {
    lo = __uint_as_float((unsigned int)(p & 0xffffffffull));
    hi = __uint_as_float((unsigned int)(p >> 32));
}

// ================= PTX helpers =================
__device__ __forceinline__ uint32_t smem_u32(const void* p) {
    uint32_t a;
    asm("{ .reg .u64 t; cvta.to.shared.u64 t, %1; cvt.u32.u64 %0, t; }" : "=r"(a) : "l"(p));
    return a;
}

#define LDSM4(r, addr) \
    asm volatile("ldmatrix.sync.aligned.m8n8.x4.shared.b16 {%0,%1,%2,%3}, [%4];" \
        : "=r"((r)[0]), "=r"((r)[1]), "=r"((r)[2]), "=r"((r)[3]) : "r"(addr))
#define LDSM2(r, addr) \
    asm volatile("ldmatrix.sync.aligned.m8n8.x2.shared.b16 {%0,%1}, [%2];" \
        : "=r"((r)[0]), "=r"((r)[1]) : "r"(addr))

// fp16 MMA: m16n8k16, f32 accumulate
#define MMA16816(c, a, b0, b1) \
    asm volatile("mma.sync.aligned.m16n8k16.row.col.f32.f16.f16.f32 " \
        "{%0,%1,%2,%3}, {%4,%5,%6,%7}, {%8,%9}, {%0,%1,%2,%3};" \
        : "+f"((c)[0]), "+f"((c)[1]), "+f"((c)[2]), "+f"((c)[3]) \
        : "r"((a)[0]), "r"((a)[1]), "r"((a)[2]), "r"((a)[3]), "r"(b0), "r"(b1))

// ================= shared memory layout (rnn kernel) =================
struct MiscS {
    float red[16][2 * KK];     // per-warp partials (sq | du)
    float gbuf[KK];
    float rbuf[KK];
    unsigned short slist[SS];
};
#define TILEB (24 * PITCHB)
#define OFF_USTAGE 0                              // U^T hi fp16 [256 e][256 d], one-time staging
#define OFF_HT0 (256 * PITCHB)
#define OFF_HT1 (OFF_HT0 + TILEB)
#define OFF_KV  (OFF_HT1 + TILEB)
#define OFF_MISC (OFF_KV + KK * KVP * 4)
#define SMEM_TOT ((int)(OFF_MISC + sizeof(MiscS)))

// ================= kernel 0: mask compaction to global =================
__global__ void __launch_bounds__(256) mask_kernel(const int* __restrict__ mask) {
    __shared__ int wcnt[8];
    const int b = blockIdx.x;
    const int tid = threadIdx.x;
    const int lane = tid & 31, w = tid >> 5;

    int total = 0;
    for (int r = 0; r < 2; r++) {
        const int idx = r * 256 + tid;
        const int m = (mask[b * SS + idx] != 0);
        const unsigned bal = __ballot_sync(0xffffffffu, m);
        const int pre = __popc(bal & ((1u << lane) - 1));
        if (lane == 0) wcnt[w] = __popc(bal);
        __syncthreads();
        int woff = 0;
        for (int ww = 0; ww < w; ww++) woff += wcnt[ww];
        if (m) g_slist[(size_t)b * SS + total + woff + pre] = (unsigned short)idx;
        int rt = 0;
#pragma unroll
        for (int ww = 0; ww < 8; ww++) rt += wcnt[ww];
        total += rt;
        __syncthreads();
    }
    if (tid == 0) g_nact[b] = total;
}

// ================= kernel 1: xW for ACTIVE steps only (f32x2, proven) =================
__global__ void __launch_bounds__(256) xw_kernel(const float* __restrict__ X,
                                                 const float* __restrict__ W) {
    __shared__ float xt[DD][34];
    __shared__ unsigned short sl[32];
    const int cta = blockIdx.x;
    const int b = cta >> 4;
    const int s0 = (cta & 15) * 32;     // compact row base
    const int tid = threadIdx.x;

    const int n_act = g_nact[b];
    if (s0 >= n_act) return;

    if (tid < 32)
        sl[tid] = (s0 + tid < n_act) ? g_slist[(size_t)b * SS + s0 + tid] : (unsigned short)0;
    __syncthreads();

    for (int idx = tid; idx < 32 * DD; idx += 256) {
        const int ss = idx >> 8, d = idx & 255;
        xt[d][ss] = X[((size_t)b * SS + sl[ss]) * DD + d];
    }
    __syncthreads();

    unsigned long long acc[16];
#pragma unroll
    for (int i = 0; i < 16; i++) acc[i] = 0ull;

    float ua[4], ub[4], un[4];
#pragma unroll
    for (int j = 0; j < 4; j++) ua[j] = W[j * DD + tid];
#pragma unroll
    for (int j = 0; j < 4; j++) ub[j] = W[(4 + j) * DD + tid];
    for (int db = 0; db < 64; db++) {
        const int dn = db * 4 + 8;
        if (dn < DD) {
#pragma unroll
            for (int j = 0; j < 4; j++) un[j] = W[(dn + j) * DD + tid];
        } else {
#pragma unroll
            for (int j = 0; j < 4; j++) un[j] = 0.f;
        }
#pragma unroll
        for (int dd = 0; dd < 4; dd++) {
            const int d = db * 4 + dd;
            const unsigned long long* xr = (const unsigned long long*)xt[d];
            unsigned long long ww = pk2(ua[dd]);
#pragma unroll
            for (int j = 0; j < 16; j++) acc[j] = f2fma(xr[j], ww, acc[j]);
        }
#pragma unroll
        for (int j = 0; j < 4; j++) { ua[j] = ub[j]; ub[j] = un[j]; }
    }
#pragma unroll
    for (int j = 0; j < 16; j++) {
        float lo, hi;
        upk2(acc[j], lo, hi);
        const int r0 = s0 + 2 * j, r1 = s0 + 2 * j + 1;
        if (r0 < n_act) g_xw[((size_t)b * SS + r0) * DD + tid] = lo;
        if (r1 < n_act) g_xw[((size_t)b * SS + r1) * DD + tid] = hi;
    }
}

// ================= kernel 1b: xk for ACTIVE steps only =================
__global__ void __launch_bounds__(256) xk_kernel(const float* __restrict__ X,
                                                 const float* __restrict__ keys) {
    const int b = blockIdx.x >> 6;
    const int i = ((blockIdx.x & 63) << 3) + (threadIdx.x >> 5);
    const int lane = threadIdx.x & 31;
    if (i >= g_nact[b]) return;    // whole warp shares i
    const int s = g_slist[(size_t)b * SS + i];
    const float* x = X + ((size_t)b * SS + s) * DD;
    const float* kb = keys + (size_t)b * KK * DD;

    float xr[8];
#pragma unroll
    for (int c = 0; c < 8; c++) xr[c] = x[lane + 32 * c];

    float pk[KK];
#pragma unroll
    for (int k = 0; k < KK; k++) {
        float p = 0.f;
#pragma unroll
        for (int c = 0; c < 8; c++) p = fmaf(xr[c], kb[k * DD + lane + 32 * c], p);
        pk[k] = p;
    }
#pragma unroll
    for (int o = 16; o; o >>= 1)
#pragma unroll
        for (int k = 0; k < KK; k++) pk[k] += __shfl_xor_sync(0xffffffffu, pk[k], o);

    if (lane < KK)
        g_xk[((size_t)b * SS + i) * KK + lane] = pk[lane];
}

// ================= kernel 2: single-CTA HMMA recurrent kernel =================
// 512 threads; 16 warps x 16 e-columns. Single-pass fp16 MMA (Uhi x UPDhi),
// deferred normalization, double-buffered h tile.
// NEW: the 20-thread final reduce runs AFTER barB with no trailing barrier,
// overlapping the next step's MMA phase; barA (before the epilogue) is what
// guarantees rbuf/gbuf are ready.
__global__ void __launch_bounds__(512, 1)
rnn_mma_kernel(const float* __restrict__ X, const int* __restrict__ mask,
               const float* __restrict__ keys, const float* __restrict__ U,
               const float* __restrict__ V, float* __restrict__ out) {
    extern __shared__ __align__(16) unsigned char smraw[];
    MiscS* ms = (MiscS*)(smraw + OFF_MISC);
    float* kVs = (float*)(smraw + OFF_KV);

    const int tid = threadIdx.x;
    const int lane = tid & 31, w = tid >> 5;   // 16 warps
    const int b = blockIdx.x;
    const uint32_t smbase = smem_u32(smraw);

    const int e0 = w * 16;                      // warp's 16 e-columns
    const int gr = lane >> 2;
    const int gc = (lane & 3) * 2;
    const int eg0 = e0 + gr;
    const int eg1 = e0 + 8 + gr;

    // ---- load precomputed active list ----
    const int n_act = g_nact[b];
    for (int idx = tid; idx < SS; idx += 512)
        ms->slist[idx] = g_slist[(size_t)b * SS + idx];

    // ---- stage U^T HI (fp16, full 256 e), preload A frags (one-time) ----
    for (int idx = tid; idx < 256 * DD; idx += 512) {
        const int el = idx & 255, d = idx >> 8;
        const float f = U[(size_t)d * DD + el];
        *(unsigned short*)(smraw + OFF_USTAGE + el * PITCHB + d * 2) =
            __half_as_ushort(__float2half_rn(f));
    }
    __syncthreads();

    const uint32_t aoff = (uint32_t)(e0 + (lane & 7) + ((lane >> 3) & 1) * 8) * PITCHB
                        + (uint32_t)((lane >> 4) & 1) * 16;
    uint32_t uh[16][4];
#pragma unroll
    for (int kc = 0; kc < 16; kc++)
        LDSM4(uh[kc], smbase + OFF_USTAGE + aoff + (uint32_t)kc * 32);

    // zero both h tiles (rows 20..23 stay zero forever)
    {
        const uint4 z = make_uint4(0, 0, 0, 0);
        uint4* p = (uint4*)(smraw + OFF_HT0);
        for (int i = tid; i < (2 * TILEB) / 16; i += 512) p[i] = z;
    }

    // kV table [20][KVP] full e range; thread (kh, el): 10 k values
    {
        const int kh = tid >> 8, el = tid & 255;
        float kvv[10];
#pragma unroll
        for (int j = 0; j < 10; j++) kvv[j] = 0.f;
        const float* kr = keys + (size_t)b * KK * DD + (size_t)kh * 10 * DD;
#pragma unroll 4
        for (int d = 0; d < DD; d++) {
            const float vv = V[(size_t)d * DD + el];
#pragma unroll
            for (int j = 0; j < 10; j++) kvv[j] = fmaf(kr[j * DD + d], vv, kvv[j]);
        }
#pragma unroll
        for (int j = 0; j < 10; j++) kVs[(kh * 10 + j) * KVP + el] = kvv[j];
    }

    if (tid < KK && n_act > 0) {
        ms->gbuf[tid] = 1.f / (1.f + __expf(-g_xk[((size_t)b * SS + 0) * KK + tid]));
        ms->rbuf[tid] = 1.f;   // rinv_prev for step 0 (h=0, tile=0 -> exact)
    }
    __syncthreads();

    const uint32_t bOff4 = (uint32_t)(8 * ((lane >> 4) & 1) + (lane & 7)) * PITCHB
                         + (uint32_t)((lane >> 3) & 1) * 16;
    const uint32_t bOff2 = (uint32_t)(16 + (lane & 7)) * PITCHB
                         + (uint32_t)((lane >> 3) & 1) * 16;
    const uint32_t ht[2] = { smbase + OFF_HT0, smbase + OFF_HT1 };

    // hreg holds UNNORMALIZED upd from the previous step (0 initially)
    float hreg[3][4];
#pragma unroll
    for (int nt = 0; nt < 3; nt++)
#pragma unroll
        for (int q = 0; q < 4; q++) hreg[nt][q] = 0.f;

    for (int i = 0; i < n_act; i++) {
        const uint32_t rtile = ht[i & 1];          // holds upd_{i-1}
        const uint32_t wtile = ht[(i + 1) & 1];    // will hold upd_i
        const bool hasn = (i + 1 < n_act);
        const int sn = hasn ? (int)ms->slist[i + 1] : 0;
        const float xw0 = g_xw[((size_t)b * SS + i) * DD + eg0];
        const float xw1 = g_xw[((size_t)b * SS + i) * DD + eg1];
        float xn0 = 0.f, xn1 = 0.f;
        if (hasn) {
            xn0 = X[((size_t)b * SS + sn) * DD + eg0];
            xn1 = X[((size_t)b * SS + sn) * DD + eg1];
        }

        float c[3][4];
#pragma unroll
        for (int nt = 0; nt < 3; nt++)
#pragma unroll
            for (int q = 0; q < 4; q++) c[nt][q] = 0.f;

        // ---- single-pass MMA: Uhi x UPDhi (unnormalized). Overlaps the
        // 20-thread reduce from the PREVIOUS step (those threads join late). ----
#pragma unroll
        for (int kc = 0; kc < 16; kc++) {
            const uint32_t dofs = (uint32_t)kc * 32;
            uint32_t bh[4], b2[2];
            LDSM4(bh, rtile + bOff4 + dofs);
            LDSM2(b2, rtile + bOff2 + dofs);
            MMA16816(c[0], uh[kc], bh[0], bh[1]);
            MMA16816(c[1], uh[kc], bh[2], bh[3]);
            MMA16816(c[2], uh[kc], b2[0], b2[1]);
        }

        __syncthreads();   // barA: rbuf/gbuf from step i-1's reduce are ready

        // ---- epilogue: deferred normalization + update + tile write + partials ----
        float sq6[6], du6[6];
#pragma unroll
        for (int nt = 0; nt < 3; nt++) {
#pragma unroll
            for (int j = 0; j < 2; j++) {
                const int k = 8 * nt + gc + j;
                const bool val = (k < KK);
                const int kk = val ? k : 0;
                const float gv = val ? ms->gbuf[kk] : 0.f;
                const float rv = ms->rbuf[kk];            // rinv_{i-1}
                const float kv0 = kVs[kk * KVP + eg0];
                const float kv1 = kVs[kk * KVP + eg1];
                float u0 = 0.f, u1 = 0.f;
                if (val) {
                    u0 = rv * hreg[nt][j] + gv * fmaxf(rv * c[nt][j] + kv0 + xw0, 0.f);
                    u1 = rv * hreg[nt][2 + j] + gv * fmaxf(rv * c[nt][2 + j] + kv1 + xw1, 0.f);
                    // write UNNORMALIZED upd to the write tile NOW (off the rinv path)
                    const uint32_t roff = (uint32_t)k * PITCHB;
                    const unsigned short b0 = __half_as_ushort(__float2half_rn(u0));
                    const unsigned short b1 = __half_as_ushort(__float2half_rn(u1));
                    asm volatile("st.shared.u16 [%0], %1;" :: "r"(wtile + roff + (uint32_t)eg0 * 2), "h"(b0) : "memory");
                    asm volatile("st.shared.u16 [%0], %1;" :: "r"(wtile + roff + (uint32_t)eg1 * 2), "h"(b1) : "memory");
                }
                hreg[nt][j] = u0;
                hreg[nt][2 + j] = u1;
                sq6[2 * nt + j] = u0 * u0 + u1 * u1;
                du6[2 * nt + j] = xn0 * u0 + xn1 * u1;
            }
        }
#pragma unroll
        for (int o = 4; o <= 16; o <<= 1)
#pragma unroll
            for (int q = 0; q < 6; q++) {
                sq6[q] += __shfl_xor_sync(0xffffffffu, sq6[q], o);
                du6[q] += __shfl_xor_sync(0xffffffffu, du6[q], o);
            }
        if (lane < 4) {
#pragma unroll
            for (int q = 0; q < 6; q++) {
                const int k = 8 * (q >> 1) + gc + (q & 1);
                if (k < KK) {
                    ms->red[w][k] = sq6[q];
                    ms->red[w][KK + k] = du6[q];
                }
            }
        }
        __syncthreads();   // barB: tile writes + red visible

        // ---- final reduce: NO trailing barrier; overlaps next step's MMA ----
        if (tid < KK) {
            float sq = 0.f, du = 0.f;
#pragma unroll
            for (int ww = 0; ww < 16; ww++) {
                sq += ms->red[ww][tid];
                du += ms->red[ww][KK + tid];
            }
            const float rinv = rsqrtf(fmaxf(sq, 1e-12f));
            ms->rbuf[tid] = rinv;
            if (hasn)
                ms->gbuf[tid] = 1.f / (1.f + __expf(-(rinv * du + g_xk[((size_t)b * SS + i + 1) * KK + tid])));
        }
    }

    __syncthreads();   // final reduce (last step) visible for emit

    // ---- emit: apply final rinv to register state ----
#pragma unroll
    for (int nt = 0; nt < 3; nt++) {
#pragma unroll
        for (int j = 0; j < 2; j++) {
            const int k = 8 * nt + gc + j;
            if (k < KK) {
                const float rv = ms->rbuf[k];
                out[((size_t)b * KK + k) * DD + eg0] = hreg[nt][j] * rv;
                out[((size_t)b * KK + k) * DD + eg1] = hreg[nt][2 + j] * rv;
            }
        }
    }
}

extern "C" void kernel_launch(void* const* d_in, const int* in_sizes, int n_in,
                              void* d_out, int out_size) {
    const float* X = (const float*)d_in[0];
    const int* mask = (const int*)d_in[1];
    const float* keys = (const float*)d_in[2];
    const float* U = (const float*)d_in[3];
    const float* V = (const float*)d_in[4];
    const float* W = (const float*)d_in[5];
    float* out = (float*)d_out;

    cudaFuncSetAttribute(rnn_mma_kernel, cudaFuncAttributeMaxDynamicSharedMemorySize, SMEM_TOT);

    mask_kernel<<<BB, 256>>>(mask);
    xw_kernel<<<BB * (SS / 32), 256>>>(X, W);
    xk_kernel<<<BB * (SS / 8), 256>>>(X, keys);
    rnn_mma_kernel<<<BB, 512, SMEM_TOT>>>(X, mask, keys, U, V, out);
}